// round 1
// baseline (speedup 1.0000x reference)
#include <cuda_runtime.h>
#include <math.h>

// Problem constants
constexpr int C_DIM   = 2048;
constexpr int NH      = 16;
constexpr int HD      = 128;
constexpr int SEQ     = 512;
constexpr int NB      = 16;
constexpr int MROWS   = NB * SEQ;        // 8192
constexpr int QKV_N   = 3 * C_DIM;       // 6144

// Scratch (static device globals — no runtime allocation)
__device__ float g_qkv[(long long)MROWS * QKV_N]; // 192 MiB
__device__ float g_y  [(long long)MROWS * C_DIM]; //  64 MiB

// ---------------------------------------------------------------------------
// SGEMM: C[M,N] = A[M,K] @ B[K,N], all row-major, fp32.
// 128x128 block tile, BK=16, 256 threads, 8x8 per-thread microtile.
// Dims are compile-time-friendly multiples (no bounds checks needed).
// ---------------------------------------------------------------------------
__global__ __launch_bounds__(256) void sgemm_kernel(
    const float* __restrict__ A, const float* __restrict__ B,
    float* __restrict__ C, int M, int N, int K)
{
    constexpr int BM = 128, BN = 128, BK = 16, TM = 8, TN = 8;
    __shared__ float As[BK][BM + 4];   // stored transposed: As[k][i]
    __shared__ float Bs[BK][BN + 4];   // Bs[k][j]

    const int tid  = threadIdx.x;
    const int brow = blockIdx.y;
    const int bcol = blockIdx.x;

    const float* Ab = A + (size_t)brow * BM * K;
    const float* Bb = B + (size_t)bcol * BN;

    // load mapping
    const int a_r = tid >> 2;            // 0..63 (+64)
    const int a_c = (tid & 3) * 4;       // float4 col within BK
    const int b_r = tid >> 5;            // 0..7 (+8)
    const int b_c = (tid & 31) * 4;

    const int ti = (tid >> 4) * TM;
    const int tj = (tid & 15) * TN;

    float acc[TM][TN];
#pragma unroll
    for (int m = 0; m < TM; ++m)
#pragma unroll
        for (int n = 0; n < TN; ++n) acc[m][n] = 0.f;

    for (int k0 = 0; k0 < K; k0 += BK) {
#pragma unroll
        for (int it = 0; it < 2; ++it) {
            int r = a_r + it * 64;
            float4 v = *(const float4*)(Ab + (size_t)r * K + k0 + a_c);
            As[a_c + 0][r] = v.x;
            As[a_c + 1][r] = v.y;
            As[a_c + 2][r] = v.z;
            As[a_c + 3][r] = v.w;
        }
#pragma unroll
        for (int it = 0; it < 2; ++it) {
            int r = b_r + it * 8;
            float4 v = *(const float4*)(Bb + (size_t)(k0 + r) * N + b_c);
            *(float4*)&Bs[r][b_c] = v;
        }
        __syncthreads();

#pragma unroll
        for (int k = 0; k < BK; ++k) {
            float4 a0 = *(const float4*)&As[k][ti];
            float4 a1 = *(const float4*)&As[k][ti + 4];
            float4 b0 = *(const float4*)&Bs[k][tj];
            float4 b1 = *(const float4*)&Bs[k][tj + 4];
            float av[TM] = {a0.x, a0.y, a0.z, a0.w, a1.x, a1.y, a1.z, a1.w};
            float bv[TN] = {b0.x, b0.y, b0.z, b0.w, b1.x, b1.y, b1.z, b1.w};
#pragma unroll
            for (int m = 0; m < TM; ++m)
#pragma unroll
                for (int n = 0; n < TN; ++n)
                    acc[m][n] = fmaf(av[m], bv[n], acc[m][n]);
        }
        __syncthreads();
    }

    float* Cb = C + (size_t)(brow * BM + ti) * N + bcol * BN + tj;
#pragma unroll
    for (int m = 0; m < TM; ++m) {
        *(float4*)(Cb + (size_t)m * N)     = make_float4(acc[m][0], acc[m][1], acc[m][2], acc[m][3]);
        *(float4*)(Cb + (size_t)m * N + 4) = make_float4(acc[m][4], acc[m][5], acc[m][6], acc[m][7]);
    }
}

// ---------------------------------------------------------------------------
// RoPE in-place on q and k slices of the qkv buffer.
// One thread per rotation pair (d, d+8), d in [0,8), first 16 dims per head.
// total threads = 8192 rows * 2 (q,k) * 16 heads * 8 pairs = 2,097,152
// ---------------------------------------------------------------------------
__global__ __launch_bounds__(256) void rope_kernel(float* __restrict__ qkv)
{
    int idx = blockIdx.x * blockDim.x + threadIdx.x;
    int d = idx & 7;
    int h = (idx >> 3) & 15;
    int w = (idx >> 7) & 1;           // 0 = q, 1 = k
    int m = idx >> 8;                 // 0..8191 (b*SEQ + t)
    int t = m & (SEQ - 1);

    size_t base = (size_t)m * QKV_N + w * C_DIM + h * HD;
    float inv = powf(10000.0f, -(float)d * 0.125f);
    float ang = (float)t * inv;
    float s, c;
    sincosf(ang, &s, &c);
    float x1 = qkv[base + d];
    float x2 = qkv[base + d + 8];
    qkv[base + d]     = x1 * c - x2 * s;
    qkv[base + d + 8] = x2 * c + x1 * s;
}

// ---------------------------------------------------------------------------
// Flash attention, causal, fp32. Q-tile 64 x K-tile 64, hd=128.
// 256 threads = 16x16; each thread: 4x4 S fragment, 4x8 O fragment.
// Q,K staged transposed (k-major) for conflict-free float4 smem reads.
// ---------------------------------------------------------------------------
constexpr int QT_LD = 68;    // 64 + pad (272B rows: float4-aligned)
constexpr int VS_LD = 132;   // 128 + pad (528B rows: float4-aligned)
constexpr int ATT_SMEM_FLOATS = 128*QT_LD + 128*QT_LD + 64*VS_LD + 64*QT_LD;
constexpr int ATT_SMEM_BYTES  = ATT_SMEM_FLOATS * 4;   // 120832

__global__ __launch_bounds__(256) void attn_kernel(
    const float* __restrict__ qkv, float* __restrict__ y)
{
    extern __shared__ float sm[];
    float* QT = sm;                       // [128][QT_LD] transposed Q
    float* KT = QT + 128 * QT_LD;         // [128][QT_LD] transposed K
    float* Vs = KT + 128 * QT_LD;         // [64][VS_LD]  row-major V
    float* Ps = Vs + 64 * VS_LD;          // [64][QT_LD]  probabilities

    const int tid = threadIdx.x;
    const int qt  = blockIdx.x;           // q tile 0..7
    const int bh  = blockIdx.y;           // 0..255
    const int b = bh >> 4, h = bh & 15;

    const float* base = qkv + (size_t)b * SEQ * QKV_N + h * HD;

    const int ti0 = (tid >> 4) * 4;       // S/O rows
    const int tx  = tid & 15;
    const int tj0 = tx * 4;               // S cols
    const int d0  = tx * 8;               // O cols

    // stage Q tile transposed
    {
        int t0 = qt * 64;
#pragma unroll
        for (int it = 0; it < 8; ++it) {
            int idx = it * 256 + tid;
            int j = idx >> 5, dv = (idx & 31) * 4;
            float4 v = *(const float4*)(base + (size_t)(t0 + j) * QKV_N + dv);
            QT[(dv + 0) * QT_LD + j] = v.x;
            QT[(dv + 1) * QT_LD + j] = v.y;
            QT[(dv + 2) * QT_LD + j] = v.z;
            QT[(dv + 3) * QT_LD + j] = v.w;
        }
    }

    float O[4][8];
    float mrow[4], lrow[4];
#pragma unroll
    for (int i = 0; i < 4; ++i) {
        mrow[i] = -1e30f; lrow[i] = 0.f;
#pragma unroll
        for (int dd = 0; dd < 8; ++dd) O[i][dd] = 0.f;
    }

    const float scale = 0.08838834764831845f;   // 1/sqrt(128)

    for (int kt = 0; kt <= qt; ++kt) {
        int t0 = kt * 64;
        // stage K (transposed) + V (row-major)
#pragma unroll
        for (int it = 0; it < 8; ++it) {
            int idx = it * 256 + tid;
            int j = idx >> 5, dv = (idx & 31) * 4;
            const float* kb = base + C_DIM + (size_t)(t0 + j) * QKV_N + dv;
            float4 v = *(const float4*)kb;
            KT[(dv + 0) * QT_LD + j] = v.x;
            KT[(dv + 1) * QT_LD + j] = v.y;
            KT[(dv + 2) * QT_LD + j] = v.z;
            KT[(dv + 3) * QT_LD + j] = v.w;
            *(float4*)&Vs[j * VS_LD + dv] = *(const float4*)(kb + C_DIM);
        }
        __syncthreads();

        // S = Q @ K^T
        float s[4][4];
#pragma unroll
        for (int i = 0; i < 4; ++i)
#pragma unroll
            for (int jj = 0; jj < 4; ++jj) s[i][jj] = 0.f;

#pragma unroll 4
        for (int k = 0; k < HD; ++k) {
            float4 a  = *(const float4*)&QT[k * QT_LD + ti0];
            float4 bb = *(const float4*)&KT[k * QT_LD + tj0];
            float av[4] = {a.x, a.y, a.z, a.w};
            float bv[4] = {bb.x, bb.y, bb.z, bb.w};
#pragma unroll
            for (int i = 0; i < 4; ++i)
#pragma unroll
                for (int jj = 0; jj < 4; ++jj)
                    s[i][jj] = fmaf(av[i], bv[jj], s[i][jj]);
        }

        // scale + causal mask + online softmax update
#pragma unroll
        for (int i = 0; i < 4; ++i) {
            int qg = qt * 64 + ti0 + i;
            float mx = -1e30f;
#pragma unroll
            for (int jj = 0; jj < 4; ++jj) {
                int kg = t0 + tj0 + jj;
                float v = (kg <= qg) ? s[i][jj] * scale : -1e30f;
                s[i][jj] = v;
                mx = fmaxf(mx, v);
            }
#pragma unroll
            for (int off = 8; off > 0; off >>= 1)
                mx = fmaxf(mx, __shfl_xor_sync(0xffffffffu, mx, off, 32));
            float mnew  = fmaxf(mrow[i], mx);
            float alpha = __expf(mrow[i] - mnew);
            float rs = 0.f;
#pragma unroll
            for (int jj = 0; jj < 4; ++jj) {
                float p = __expf(s[i][jj] - mnew);
                s[i][jj] = p;
                rs += p;
            }
#pragma unroll
            for (int off = 8; off > 0; off >>= 1)
                rs += __shfl_xor_sync(0xffffffffu, rs, off, 32);
            lrow[i] = lrow[i] * alpha + rs;
            mrow[i] = mnew;
#pragma unroll
            for (int dd = 0; dd < 8; ++dd) O[i][dd] *= alpha;
            *(float4*)&Ps[(ti0 + i) * QT_LD + tj0] =
                make_float4(s[i][0], s[i][1], s[i][2], s[i][3]);
        }
        __syncthreads();

        // O += P @ V
#pragma unroll 2
        for (int j = 0; j < 64; ++j) {
            float4 v0 = *(const float4*)&Vs[j * VS_LD + d0];
            float4 v1 = *(const float4*)&Vs[j * VS_LD + d0 + 4];
            float vv[8] = {v0.x, v0.y, v0.z, v0.w, v1.x, v1.y, v1.z, v1.w};
#pragma unroll
            for (int i = 0; i < 4; ++i) {
                float p = Ps[(ti0 + i) * QT_LD + j];
#pragma unroll
                for (int dd = 0; dd < 8; ++dd)
                    O[i][dd] = fmaf(p, vv[dd], O[i][dd]);
            }
        }
        __syncthreads();
    }

    // finalize + write y[b, t, h*128 + d]
#pragma unroll
    for (int i = 0; i < 4; ++i) {
        float inv_l = 1.0f / lrow[i];
        int tq = qt * 64 + ti0 + i;
        float* yp = y + (size_t)(b * SEQ + tq) * C_DIM + h * HD + d0;
        *(float4*)(yp)     = make_float4(O[i][0]*inv_l, O[i][1]*inv_l, O[i][2]*inv_l, O[i][3]*inv_l);
        *(float4*)(yp + 4) = make_float4(O[i][4]*inv_l, O[i][5]*inv_l, O[i][6]*inv_l, O[i][7]*inv_l);
    }
}

// ---------------------------------------------------------------------------
extern "C" void kernel_launch(void* const* d_in, const int* in_sizes, int n_in,
                              void* d_out, int out_size)
{
    const float* x    = (const float*)d_in[0];
    const float* Wqkv = (const float*)d_in[1];
    const float* Wout = (const float*)d_in[2];
    float* out = (float*)d_out;

    float *qkv = nullptr, *y = nullptr;
    cudaGetSymbolAddress((void**)&qkv, g_qkv);
    cudaGetSymbolAddress((void**)&y,   g_y);

    // 1) qkv = x @ Wqkv   (8192 x 2048 x 6144)
    sgemm_kernel<<<dim3(QKV_N / 128, MROWS / 128), 256>>>(x, Wqkv, qkv, MROWS, QKV_N, C_DIM);

    // 2) RoPE in-place on q,k
    rope_kernel<<<(MROWS * 2 * NH * 8) / 256, 256>>>(qkv);

    // 3) causal flash attention -> y [B,T,C]
    cudaFuncSetAttribute(attn_kernel, cudaFuncAttributeMaxDynamicSharedMemorySize, ATT_SMEM_BYTES);
    attn_kernel<<<dim3(SEQ / 64, NB * NH), 256, ATT_SMEM_BYTES>>>(qkv, y);

    // 4) out = y @ Wout   (8192 x 2048 x 2048)
    sgemm_kernel<<<dim3(C_DIM / 128, MROWS / 128), 256>>>(y, Wout, out, MROWS, C_DIM, C_DIM);
}

// round 4
// speedup vs baseline: 2.3995x; 2.3995x over previous
#include <cuda_runtime.h>
#include <math.h>
#include <stdint.h>

// Problem constants
constexpr int C_DIM   = 2048;
constexpr int NH      = 16;
constexpr int HD      = 128;
constexpr int SEQ     = 512;
constexpr int NB      = 16;
constexpr int MROWS   = NB * SEQ;        // 8192
constexpr int QKV_N   = 3 * C_DIM;       // 6144

// Scratch (static device globals — no runtime allocation)
__device__ float g_qkv  [(long long)MROWS * QKV_N];   // 192 MiB
__device__ float g_y    [(long long)MROWS * C_DIM];   //  64 MiB
__device__ float g_WqkvT[(long long)QKV_N * C_DIM];   //  48 MiB
__device__ float g_WoutT[(long long)C_DIM * C_DIM];   //  16 MiB

// ---------------------------------------------------------------------------
// helpers
// ---------------------------------------------------------------------------
__device__ __forceinline__ uint32_t smem_u32(const void* p) {
    return (uint32_t)__cvta_generic_to_shared(p);
}
__device__ __forceinline__ void cp_async16(uint32_t dst, const void* src) {
    asm volatile("cp.async.cg.shared.global [%0], [%1], 16;\n"
                 :: "r"(dst), "l"(src) : "memory");
}
__device__ __forceinline__ void cp_commit() {
    asm volatile("cp.async.commit_group;\n" ::: "memory");
}
template <int N>
__device__ __forceinline__ void cp_wait_group() {
    asm volatile("cp.async.wait_group %0;\n" :: "n"(N) : "memory");
}
__device__ __forceinline__ uint32_t f2tf32(float f) {
    uint32_t u;
    asm("cvt.rna.tf32.f32 %0, %1;" : "=r"(u) : "f"(f));
    return u;
}
__device__ __forceinline__ void mma16n8k8(float* c, const uint32_t* a, const uint32_t* b) {
    asm volatile(
        "mma.sync.aligned.m16n8k8.row.col.f32.tf32.tf32.f32 "
        "{%0,%1,%2,%3}, {%4,%5,%6,%7}, {%8,%9}, {%0,%1,%2,%3};"
        : "+f"(c[0]), "+f"(c[1]), "+f"(c[2]), "+f"(c[3])
        : "r"(a[0]), "r"(a[1]), "r"(a[2]), "r"(a[3]), "r"(b[0]), "r"(b[1]));
}

// ---------------------------------------------------------------------------
// Tensor-core tf32 GEMM via mma.sync:  C[M,N] = A[M,K] @ Bt[N,K]^T
// A row-major [M,K]; Bt row-major [N,K]; fp32 in/out, tf32 MMA, fp32 acc.
// CTA tile 128x128, BK=32, 8 warps (2x4), warp tile 64x32, 3-stage cp.async.
// Smem rows stride 36 floats -> fragment LDS provably bank-conflict-free.
// ---------------------------------------------------------------------------
constexpr int GM_BM = 128, GM_BN = 128, GM_BK = 32, GM_NST = 3;
constexpr int GM_LDS          = 36;                 // floats per smem row
constexpr int GM_TILE_FLOATS  = 128 * GM_LDS;       // 4608 (A or B tile)
constexpr int GM_STAGE_FLOATS = 2 * GM_TILE_FLOATS; // 9216
constexpr int GM_SMEM_BYTES   = GM_NST * GM_STAGE_FLOATS * 4;  // 110592

__global__ __launch_bounds__(256, 2) void tc_gemm_kernel(
    const float* __restrict__ A, const float* __restrict__ Bt,
    float* __restrict__ C, int M, int N, int K)
{
    extern __shared__ float smf[];
    const uint32_t smem_base = smem_u32(smf);

    const int tid  = threadIdx.x;
    const int warp = tid >> 5;
    const int lane = tid & 31;
    const int m0   = blockIdx.y * GM_BM;
    const int n0   = blockIdx.x * GM_BN;
    const int wm   = (warp >> 2) * 64;   // warp M offset within CTA
    const int wn   = (warp & 3) * 32;    // warp N offset within CTA
    const int qr   = lane >> 2;          // fragment row/col helpers
    const int qc   = lane & 3;

    float acc[4][4][4];
#pragma unroll
    for (int mi = 0; mi < 4; ++mi)
#pragma unroll
        for (int ni = 0; ni < 4; ++ni)
#pragma unroll
            for (int r = 0; r < 4; ++r) acc[mi][ni][r] = 0.f;

    const int NITER = K / GM_BK;

    auto load_stage = [&](int ki) {
        const int k0  = ki * GM_BK;
        const int buf = ki % GM_NST;
        const uint32_t sa = smem_base + buf * GM_STAGE_FLOATS * 4;
        const uint32_t sb = sa + GM_TILE_FLOATS * 4;
#pragma unroll
        for (int it = 0; it < 4; ++it) {
            int idx = it * 256 + tid;
            int r = idx >> 3, c = idx & 7;
            cp_async16(sa + (uint32_t)(r * GM_LDS + c * 4) * 4,
                       A + (size_t)(m0 + r) * K + k0 + c * 4);
        }
#pragma unroll
        for (int it = 0; it < 4; ++it) {
            int idx = it * 256 + tid;
            int r = idx >> 3, c = idx & 7;
            cp_async16(sb + (uint32_t)(r * GM_LDS + c * 4) * 4,
                       Bt + (size_t)(n0 + r) * K + k0 + c * 4);
        }
    };

    load_stage(0); cp_commit();
    load_stage(1); cp_commit();

    for (int i = 0; i < NITER; ++i) {
        cp_wait_group<1>();
        __syncthreads();

        if (i + 2 < NITER) load_stage(i + 2);
        cp_commit();

        const float* As = smf + (i % GM_NST) * GM_STAGE_FLOATS;
        const float* Bs = As + GM_TILE_FLOATS;

#pragma unroll
        for (int ks = 0; ks < 4; ++ks) {
            const int cc = ks * 8 + qc;
            uint32_t af[4][4];
            uint32_t bf[4][2];
#pragma unroll
            for (int mi = 0; mi < 4; ++mi) {
                int r = wm + mi * 16 + qr;
                af[mi][0] = f2tf32(As[r * GM_LDS + cc]);
                af[mi][1] = f2tf32(As[(r + 8) * GM_LDS + cc]);
                af[mi][2] = f2tf32(As[r * GM_LDS + cc + 4]);
                af[mi][3] = f2tf32(As[(r + 8) * GM_LDS + cc + 4]);
            }
#pragma unroll
            for (int ni = 0; ni < 4; ++ni) {
                int n = wn + ni * 8 + qr;
                bf[ni][0] = f2tf32(Bs[n * GM_LDS + cc]);
                bf[ni][1] = f2tf32(Bs[n * GM_LDS + cc + 4]);
            }
#pragma unroll
            for (int mi = 0; mi < 4; ++mi)
#pragma unroll
                for (int ni = 0; ni < 4; ++ni)
                    mma16n8k8(acc[mi][ni], af[mi], bf[ni]);
        }
        __syncthreads();
    }

    // epilogue: direct global stores (float2 per fragment half)
#pragma unroll
    for (int mi = 0; mi < 4; ++mi) {
#pragma unroll
        for (int ni = 0; ni < 4; ++ni) {
            int row = m0 + wm + mi * 16 + qr;
            int col = n0 + wn + ni * 8 + 2 * qc;
            *(float2*)&C[(size_t)row * N + col] =
                make_float2(acc[mi][ni][0], acc[mi][ni][1]);
            *(float2*)&C[(size_t)(row + 8) * N + col] =
                make_float2(acc[mi][ni][2], acc[mi][ni][3]);
        }
    }
}

// ---------------------------------------------------------------------------
// Tiled transpose: out[c][r] = in[r][c].  in: [R, C]; out: [C, R].
// ---------------------------------------------------------------------------
__global__ __launch_bounds__(256) void transpose_kernel(
    const float* __restrict__ in, float* __restrict__ out, int R, int Ccols)
{
    __shared__ float t[32][33];
    int c0 = blockIdx.x * 32, r0 = blockIdx.y * 32;
    int x = c0 + threadIdx.x;
#pragma unroll
    for (int i = threadIdx.y; i < 32; i += 8)
        t[i][threadIdx.x] = in[(size_t)(r0 + i) * Ccols + x];
    __syncthreads();
    int ox = r0 + threadIdx.x;
#pragma unroll
    for (int i = threadIdx.y; i < 32; i += 8)
        out[(size_t)(c0 + i) * R + ox] = t[threadIdx.x][i];
}

// ---------------------------------------------------------------------------
// RoPE in-place on q and k slices of the qkv buffer.
// ---------------------------------------------------------------------------
__global__ __launch_bounds__(256) void rope_kernel(float* __restrict__ qkv)
{
    int idx = blockIdx.x * blockDim.x + threadIdx.x;
    int d = idx & 7;
    int h = (idx >> 3) & 15;
    int w = (idx >> 7) & 1;           // 0 = q, 1 = k
    int m = idx >> 8;                 // 0..8191 (b*SEQ + t)
    int t = m & (SEQ - 1);

    size_t base = (size_t)m * QKV_N + w * C_DIM + h * HD;
    float inv = powf(10000.0f, -(float)d * 0.125f);
    float ang = (float)t * inv;
    float s, c;
    sincosf(ang, &s, &c);
    float x1 = qkv[base + d];
    float x2 = qkv[base + d + 8];
    qkv[base + d]     = x1 * c - x2 * s;
    qkv[base + d + 8] = x2 * c + x1 * s;
}

// ---------------------------------------------------------------------------
// Flash attention, causal, fp32 (unchanged from round 1 passing version)
// ---------------------------------------------------------------------------
constexpr int QT_LD = 68;
constexpr int VS_LD = 132;
constexpr int ATT_SMEM_FLOATS = 128*QT_LD + 128*QT_LD + 64*VS_LD + 64*QT_LD;
constexpr int ATT_SMEM_BYTES  = ATT_SMEM_FLOATS * 4;

__global__ __launch_bounds__(256) void attn_kernel(
    const float* __restrict__ qkv, float* __restrict__ y)
{
    extern __shared__ float smf[];
    float* QT = smf;
    float* KT = QT + 128 * QT_LD;
    float* Vs = KT + 128 * QT_LD;
    float* Ps = Vs + 64 * VS_LD;

    const int tid = threadIdx.x;
    const int qt  = blockIdx.x;
    const int bh  = blockIdx.y;
    const int b = bh >> 4, h = bh & 15;

    const float* base = qkv + (size_t)b * SEQ * QKV_N + h * HD;

    const int ti0 = (tid >> 4) * 4;
    const int tx  = tid & 15;
    const int tj0 = tx * 4;
    const int d0  = tx * 8;

    {
        int t0 = qt * 64;
#pragma unroll
        for (int it = 0; it < 8; ++it) {
            int idx = it * 256 + tid;
            int j = idx >> 5, dv = (idx & 31) * 4;
            float4 v = *(const float4*)(base + (size_t)(t0 + j) * QKV_N + dv);
            QT[(dv + 0) * QT_LD + j] = v.x;
            QT[(dv + 1) * QT_LD + j] = v.y;
            QT[(dv + 2) * QT_LD + j] = v.z;
            QT[(dv + 3) * QT_LD + j] = v.w;
        }
    }

    float O[4][8];
    float mrow[4], lrow[4];
#pragma unroll
    for (int i = 0; i < 4; ++i) {
        mrow[i] = -1e30f; lrow[i] = 0.f;
#pragma unroll
        for (int dd = 0; dd < 8; ++dd) O[i][dd] = 0.f;
    }

    const float scale = 0.08838834764831845f;

    for (int kt = 0; kt <= qt; ++kt) {
        int t0 = kt * 64;
#pragma unroll
        for (int it = 0; it < 8; ++it) {
            int idx = it * 256 + tid;
            int j = idx >> 5, dv = (idx & 31) * 4;
            const float* kb = base + C_DIM + (size_t)(t0 + j) * QKV_N + dv;
            float4 v = *(const float4*)kb;
            KT[(dv + 0) * QT_LD + j] = v.x;
            KT[(dv + 1) * QT_LD + j] = v.y;
            KT[(dv + 2) * QT_LD + j] = v.z;
            KT[(dv + 3) * QT_LD + j] = v.w;
            *(float4*)&Vs[j * VS_LD + dv] = *(const float4*)(kb + C_DIM);
        }
        __syncthreads();

        float s[4][4];
#pragma unroll
        for (int i = 0; i < 4; ++i)
#pragma unroll
            for (int jj = 0; jj < 4; ++jj) s[i][jj] = 0.f;

#pragma unroll 4
        for (int k = 0; k < HD; ++k) {
            float4 a  = *(const float4*)&QT[k * QT_LD + ti0];
            float4 bb = *(const float4*)&KT[k * QT_LD + tj0];
            float av[4] = {a.x, a.y, a.z, a.w};
            float bv[4] = {bb.x, bb.y, bb.z, bb.w};
#pragma unroll
            for (int i = 0; i < 4; ++i)
#pragma unroll
                for (int jj = 0; jj < 4; ++jj)
                    s[i][jj] = fmaf(av[i], bv[jj], s[i][jj]);
        }

#pragma unroll
        for (int i = 0; i < 4; ++i) {
            int qg = qt * 64 + ti0 + i;
            float mx = -1e30f;
#pragma unroll
            for (int jj = 0; jj < 4; ++jj) {
                int kg = t0 + tj0 + jj;
                float v = (kg <= qg) ? s[i][jj] * scale : -1e30f;
                s[i][jj] = v;
                mx = fmaxf(mx, v);
            }
#pragma unroll
            for (int off = 8; off > 0; off >>= 1)
                mx = fmaxf(mx, __shfl_xor_sync(0xffffffffu, mx, off, 32));
            float mnew  = fmaxf(mrow[i], mx);
            float alpha = __expf(mrow[i] - mnew);
            float rs = 0.f;
#pragma unroll
            for (int jj = 0; jj < 4; ++jj) {
                float p = __expf(s[i][jj] - mnew);
                s[i][jj] = p;
                rs += p;
            }
#pragma unroll
            for (int off = 8; off > 0; off >>= 1)
                rs += __shfl_xor_sync(0xffffffffu, rs, off, 32);
            lrow[i] = lrow[i] * alpha + rs;
            mrow[i] = mnew;
#pragma unroll
            for (int dd = 0; dd < 8; ++dd) O[i][dd] *= alpha;
            *(float4*)&Ps[(ti0 + i) * QT_LD + tj0] =
                make_float4(s[i][0], s[i][1], s[i][2], s[i][3]);
        }
        __syncthreads();

#pragma unroll 2
        for (int j = 0; j < 64; ++j) {
            float4 v0 = *(const float4*)&Vs[j * VS_LD + d0];
            float4 v1 = *(const float4*)&Vs[j * VS_LD + d0 + 4];
            float vv[8] = {v0.x, v0.y, v0.z, v0.w, v1.x, v1.y, v1.z, v1.w};
#pragma unroll
            for (int i = 0; i < 4; ++i) {
                float p = Ps[(ti0 + i) * QT_LD + j];
#pragma unroll
                for (int dd = 0; dd < 8; ++dd)
                    O[i][dd] = fmaf(p, vv[dd], O[i][dd]);
            }
        }
        __syncthreads();
    }

#pragma unroll
    for (int i = 0; i < 4; ++i) {
        float inv_l = 1.0f / lrow[i];
        int tq = qt * 64 + ti0 + i;
        float* yp = y + (size_t)(b * SEQ + tq) * C_DIM + h * HD + d0;
        *(float4*)(yp)     = make_float4(O[i][0]*inv_l, O[i][1]*inv_l, O[i][2]*inv_l, O[i][3]*inv_l);
        *(float4*)(yp + 4) = make_float4(O[i][4]*inv_l, O[i][5]*inv_l, O[i][6]*inv_l, O[i][7]*inv_l);
    }
}

// ---------------------------------------------------------------------------
extern "C" void kernel_launch(void* const* d_in, const int* in_sizes, int n_in,
                              void* d_out, int out_size)
{
    const float* x    = (const float*)d_in[0];
    const float* Wqkv = (const float*)d_in[1];
    const float* Wout = (const float*)d_in[2];
    float* out = (float*)d_out;

    float *qkv = nullptr, *y = nullptr, *wqkvT = nullptr, *woutT = nullptr;
    cudaGetSymbolAddress((void**)&qkv,   g_qkv);
    cudaGetSymbolAddress((void**)&y,     g_y);
    cudaGetSymbolAddress((void**)&wqkvT, g_WqkvT);
    cudaGetSymbolAddress((void**)&woutT, g_WoutT);

    static bool attr_set = false;
    if (!attr_set) {
        cudaFuncSetAttribute(tc_gemm_kernel, cudaFuncAttributeMaxDynamicSharedMemorySize, GM_SMEM_BYTES);
        cudaFuncSetAttribute(attn_kernel,    cudaFuncAttributeMaxDynamicSharedMemorySize, ATT_SMEM_BYTES);
        attr_set = true;
    }

    // 0) transpose weights to K-major (B^T) layout
    transpose_kernel<<<dim3(QKV_N / 32, C_DIM / 32), dim3(32, 8)>>>(Wqkv, wqkvT, C_DIM, QKV_N);
    transpose_kernel<<<dim3(C_DIM / 32, C_DIM / 32), dim3(32, 8)>>>(Wout, woutT, C_DIM, C_DIM);

    // 1) qkv = x @ Wqkv  (tf32 mma.sync)
    tc_gemm_kernel<<<dim3(QKV_N / GM_BN, MROWS / GM_BM), 256, GM_SMEM_BYTES>>>(
        x, wqkvT, qkv, MROWS, QKV_N, C_DIM);

    // 2) RoPE in-place on q,k
    rope_kernel<<<(MROWS * 2 * NH * 8) / 256, 256>>>(qkv);

    // 3) causal flash attention -> y [B,T,C]
    attn_kernel<<<dim3(SEQ / 64, NB * NH), 256, ATT_SMEM_BYTES>>>(qkv, y);

    // 4) out = y @ Wout  (tf32 mma.sync)
    tc_gemm_kernel<<<dim3(C_DIM / GM_BN, MROWS / GM_BM), 256, GM_SMEM_BYTES>>>(
        y, woutT, out, MROWS, C_DIM, C_DIM);
}

// round 6
// speedup vs baseline: 3.0975x; 1.2909x over previous
#include <cuda_runtime.h>
#include <math.h>
#include <stdint.h>

// Problem constants
constexpr int C_DIM   = 2048;
constexpr int NH      = 16;
constexpr int HD      = 128;
constexpr int SEQ     = 512;
constexpr int NB      = 16;
constexpr int MROWS   = NB * SEQ;        // 8192
constexpr int QKV_N   = 3 * C_DIM;       // 6144

// Scratch (static device globals — no runtime allocation)
__device__ float g_qkv  [(long long)MROWS * QKV_N];   // 192 MiB
__device__ float g_y    [(long long)MROWS * C_DIM];   //  64 MiB
__device__ float g_WqkvT[(long long)QKV_N * C_DIM];   //  48 MiB
__device__ float g_WoutT[(long long)C_DIM * C_DIM];   //  16 MiB

// ---------------------------------------------------------------------------
// helpers
// ---------------------------------------------------------------------------
__device__ __forceinline__ uint32_t smem_u32(const void* p) {
    return (uint32_t)__cvta_generic_to_shared(p);
}
__device__ __forceinline__ void cp_async16(uint32_t dst, const void* src) {
    asm volatile("cp.async.cg.shared.global [%0], [%1], 16;\n"
                 :: "r"(dst), "l"(src) : "memory");
}
__device__ __forceinline__ void cp_commit() {
    asm volatile("cp.async.commit_group;\n" ::: "memory");
}
template <int N>
__device__ __forceinline__ void cp_wait_group() {
    asm volatile("cp.async.wait_group %0;\n" :: "n"(N) : "memory");
}
__device__ __forceinline__ uint32_t f2tf32(float f) {
    uint32_t u;
    asm("cvt.rna.tf32.f32 %0, %1;" : "=r"(u) : "f"(f));
    return u;
}
__device__ __forceinline__ void mma16n8k8(float* c, const uint32_t* a, const uint32_t* b) {
    asm volatile(
        "mma.sync.aligned.m16n8k8.row.col.f32.tf32.tf32.f32 "
        "{%0,%1,%2,%3}, {%4,%5,%6,%7}, {%8,%9}, {%0,%1,%2,%3};"
        : "+f"(c[0]), "+f"(c[1]), "+f"(c[2]), "+f"(c[3])
        : "r"(a[0]), "r"(a[1]), "r"(a[2]), "r"(a[3]), "r"(b[0]), "r"(b[1]));
}

// ---------------------------------------------------------------------------
// Tensor-core tf32 GEMM via mma.sync:  C[M,N] = A[M,K] @ Bt[N,K]^T
// roundOut: epilogue rounds outputs to tf32 (so consumers skip cvt).
// ---------------------------------------------------------------------------
constexpr int GM_BM = 128, GM_BN = 128, GM_BK = 32, GM_NST = 3;
constexpr int GM_LDS          = 36;
constexpr int GM_TILE_FLOATS  = 128 * GM_LDS;       // 4608
constexpr int GM_STAGE_FLOATS = 2 * GM_TILE_FLOATS; // 9216
constexpr int GM_SMEM_BYTES   = GM_NST * GM_STAGE_FLOATS * 4;  // 110592

__global__ __launch_bounds__(256, 2) void tc_gemm_kernel(
    const float* __restrict__ A, const float* __restrict__ Bt,
    float* __restrict__ C, int M, int N, int K, int roundOut)
{
    extern __shared__ float smf[];
    const uint32_t smem_base = smem_u32(smf);

    const int tid  = threadIdx.x;
    const int warp = tid >> 5;
    const int lane = tid & 31;
    const int m0   = blockIdx.y * GM_BM;
    const int n0   = blockIdx.x * GM_BN;
    const int wm   = (warp >> 2) * 64;
    const int wn   = (warp & 3) * 32;
    const int qr   = lane >> 2;
    const int qc   = lane & 3;

    float acc[4][4][4];
#pragma unroll
    for (int mi = 0; mi < 4; ++mi)
#pragma unroll
        for (int ni = 0; ni < 4; ++ni)
#pragma unroll
            for (int r = 0; r < 4; ++r) acc[mi][ni][r] = 0.f;

    const int NITER = K / GM_BK;

    auto load_stage = [&](int ki) {
        const int k0  = ki * GM_BK;
        const int buf = ki % GM_NST;
        const uint32_t sa = smem_base + buf * GM_STAGE_FLOATS * 4;
        const uint32_t sb = sa + GM_TILE_FLOATS * 4;
#pragma unroll
        for (int it = 0; it < 4; ++it) {
            int idx = it * 256 + tid;
            int r = idx >> 3, c = idx & 7;
            cp_async16(sa + (uint32_t)(r * GM_LDS + c * 4) * 4,
                       A + (size_t)(m0 + r) * K + k0 + c * 4);
        }
#pragma unroll
        for (int it = 0; it < 4; ++it) {
            int idx = it * 256 + tid;
            int r = idx >> 3, c = idx & 7;
            cp_async16(sb + (uint32_t)(r * GM_LDS + c * 4) * 4,
                       Bt + (size_t)(n0 + r) * K + k0 + c * 4);
        }
    };

    load_stage(0); cp_commit();
    load_stage(1); cp_commit();

    for (int i = 0; i < NITER; ++i) {
        cp_wait_group<1>();
        __syncthreads();

        if (i + 2 < NITER) load_stage(i + 2);
        cp_commit();

        const float* As = smf + (i % GM_NST) * GM_STAGE_FLOATS;
        const float* Bs = As + GM_TILE_FLOATS;

#pragma unroll
        for (int ks = 0; ks < 4; ++ks) {
            const int cc = ks * 8 + qc;
            uint32_t af[4][4];
            uint32_t bf[4][2];
#pragma unroll
            for (int mi = 0; mi < 4; ++mi) {
                int r = wm + mi * 16 + qr;
                af[mi][0] = f2tf32(As[r * GM_LDS + cc]);
                af[mi][1] = f2tf32(As[(r + 8) * GM_LDS + cc]);
                af[mi][2] = f2tf32(As[r * GM_LDS + cc + 4]);
                af[mi][3] = f2tf32(As[(r + 8) * GM_LDS + cc + 4]);
            }
#pragma unroll
            for (int ni = 0; ni < 4; ++ni) {
                int n = wn + ni * 8 + qr;
                bf[ni][0] = f2tf32(Bs[n * GM_LDS + cc]);
                bf[ni][1] = f2tf32(Bs[n * GM_LDS + cc + 4]);
            }
#pragma unroll
            for (int mi = 0; mi < 4; ++mi)
#pragma unroll
                for (int ni = 0; ni < 4; ++ni)
                    mma16n8k8(acc[mi][ni], af[mi], bf[ni]);
        }
        __syncthreads();
    }

#pragma unroll
    for (int mi = 0; mi < 4; ++mi) {
#pragma unroll
        for (int ni = 0; ni < 4; ++ni) {
            int row = m0 + wm + mi * 16 + qr;
            int col = n0 + wn + ni * 8 + 2 * qc;
            float v0 = acc[mi][ni][0], v1 = acc[mi][ni][1];
            float v2 = acc[mi][ni][2], v3 = acc[mi][ni][3];
            if (roundOut) {
                v0 = __uint_as_float(f2tf32(v0));
                v1 = __uint_as_float(f2tf32(v1));
                v2 = __uint_as_float(f2tf32(v2));
                v3 = __uint_as_float(f2tf32(v3));
            }
            *(float2*)&C[(size_t)row * N + col]       = make_float2(v0, v1);
            *(float2*)&C[(size_t)(row + 8) * N + col] = make_float2(v2, v3);
        }
    }
}

// ---------------------------------------------------------------------------
// Tiled transpose: out[c][r] = in[r][c].
// ---------------------------------------------------------------------------
__global__ __launch_bounds__(256) void transpose_kernel(
    const float* __restrict__ in, float* __restrict__ out, int R, int Ccols)
{
    __shared__ float t[32][33];
    int c0 = blockIdx.x * 32, r0 = blockIdx.y * 32;
    int x = c0 + threadIdx.x;
#pragma unroll
    for (int i = threadIdx.y; i < 32; i += 8)
        t[i][threadIdx.x] = in[(size_t)(r0 + i) * Ccols + x];
    __syncthreads();
    int ox = r0 + threadIdx.x;
#pragma unroll
    for (int i = threadIdx.y; i < 32; i += 8)
        out[(size_t)(c0 + i) * R + ox] = t[threadIdx.x][i];
}

// ---------------------------------------------------------------------------
// RoPE in-place; outputs rounded to tf32 (attention consumes raw bits).
// ---------------------------------------------------------------------------
__global__ __launch_bounds__(256) void rope_kernel(float* __restrict__ qkv)
{
    int idx = blockIdx.x * blockDim.x + threadIdx.x;
    int d = idx & 7;
    int h = (idx >> 3) & 15;
    int w = (idx >> 7) & 1;
    int m = idx >> 8;
    int t = m & (SEQ - 1);

    size_t base = (size_t)m * QKV_N + w * C_DIM + h * HD;
    float inv = powf(10000.0f, -(float)d * 0.125f);
    float ang = (float)t * inv;
    float s, c;
    sincosf(ang, &s, &c);
    float x1 = qkv[base + d];
    float x2 = qkv[base + d + 8];
    qkv[base + d]     = __uint_as_float(f2tf32(x1 * c - x2 * s));
    qkv[base + d + 8] = __uint_as_float(f2tf32(x2 * c + x1 * s));
}

// ---------------------------------------------------------------------------
// Tensor-core flash attention (causal), tf32 mma.sync.
// CTA: 128 q-rows of one (b,h). 8 warps; warp tile = 16 q-rows x full width.
// Q frags in registers; K/V double-buffered cp.async; P bounced via smem.
// Inputs qkv are already tf32-rounded (GEMM epilogue + rope) -> no cvt here.
// ---------------------------------------------------------------------------
constexpr int AT_KLD = 132;   // K (and staged Q) row pitch (floats)
constexpr int AT_VLD = 136;   // V row pitch
constexpr int AT_PLD = 68;    // P row pitch
constexpr int AT_K0 = 0;
constexpr int AT_K1 = AT_K0 + 64 * AT_KLD;            // 8448
constexpr int AT_V0 = AT_K1 + 64 * AT_KLD;            // 16896
constexpr int AT_V1 = AT_V0 + 64 * AT_VLD;            // 25600
constexpr int AT_P  = AT_V1 + 64 * AT_VLD;            // 34304
constexpr int AT_SMEM_FLOATS = AT_P + 8 * 16 * AT_PLD;  // 43008
constexpr int AT_SMEM_BYTES  = AT_SMEM_FLOATS * 4;      // 172032

__global__ __launch_bounds__(256, 1) void attn_kernel(
    const float* __restrict__ qkv, float* __restrict__ y)
{
    extern __shared__ float smf[];
    const uint32_t smem_base = smem_u32(smf);
    const int tid  = threadIdx.x;
    const int warp = tid >> 5;
    const int lane = tid & 31;
    const int qr   = lane >> 2;
    const int qc   = lane & 3;
    const int qt   = blockIdx.x;          // q tile (128 rows) 0..3
    const int bh   = blockIdx.y;
    const int b = bh >> 4, h = bh & 15;

    const float* base = qkv + (size_t)b * SEQ * QKV_N + h * HD;
    const int q0 = qt * 128;

    // ---- stage Q (128 x 128) into V0/V1 overlay region, pitch AT_KLD
    {
#pragma unroll
        for (int it = 0; it < 16; ++it) {
            int idx = it * 256 + tid;
            int r = idx >> 5, c4 = idx & 31;
            cp_async16(smem_base + (uint32_t)(AT_V0 + r * AT_KLD + c4 * 4) * 4,
                       base + (size_t)(q0 + r) * QKV_N + c4 * 4);
        }
        cp_commit(); cp_wait_group<0>(); __syncthreads();
    }
    // extract Q fragments (already tf32 bits)
    uint32_t qf[16][4];
    {
        const uint32_t* Qs = (const uint32_t*)(smf + AT_V0) + warp * 16 * AT_KLD;
#pragma unroll
        for (int ks = 0; ks < 16; ++ks) {
            int cc = ks * 8 + qc;
            qf[ks][0] = Qs[qr * AT_KLD + cc];
            qf[ks][1] = Qs[(qr + 8) * AT_KLD + cc];
            qf[ks][2] = Qs[qr * AT_KLD + cc + 4];
            qf[ks][3] = Qs[(qr + 8) * AT_KLD + cc + 4];
        }
    }
    __syncthreads();

    float O[16][4];
#pragma unroll
    for (int dt = 0; dt < 16; ++dt)
#pragma unroll
        for (int r = 0; r < 4; ++r) O[dt][r] = 0.f;
    float m[2] = {-1e30f, -1e30f}, l[2] = {0.f, 0.f};

    const int nkt = 2 * qt + 2;

    auto load_kv = [&](int kt) {
        int buf = kt & 1;
        int t0  = kt * 64;
        const uint32_t kb = smem_base + (uint32_t)(buf ? AT_K1 : AT_K0) * 4;
        const uint32_t vb = smem_base + (uint32_t)(buf ? AT_V1 : AT_V0) * 4;
#pragma unroll
        for (int it = 0; it < 8; ++it) {
            int idx = it * 256 + tid;
            int r = idx >> 5, c4 = idx & 31;
            cp_async16(kb + (uint32_t)(r * AT_KLD + c4 * 4) * 4,
                       base + C_DIM + (size_t)(t0 + r) * QKV_N + c4 * 4);
        }
#pragma unroll
        for (int it = 0; it < 8; ++it) {
            int idx = it * 256 + tid;
            int r = idx >> 5, c4 = idx & 31;
            cp_async16(vb + (uint32_t)(r * AT_VLD + c4 * 4) * 4,
                       base + 2 * C_DIM + (size_t)(t0 + r) * QKV_N + c4 * 4);
        }
    };

    load_kv(0); cp_commit();
    load_kv(1); cp_commit();

    const int qbase_w = q0 + warp * 16;
    uint32_t* Pw = (uint32_t*)(smf + AT_P) + warp * 16 * AT_PLD;
    const float scl = 0.08838834764831845f;   // 1/sqrt(128)

    for (int kt = 0; kt < nkt; ++kt) {
        cp_wait_group<1>();
        __syncthreads();
        const uint32_t* Ks = (const uint32_t*)(smf + ((kt & 1) ? AT_K1 : AT_K0));
        const uint32_t* Vs = (const uint32_t*)(smf + ((kt & 1) ? AT_V1 : AT_V0));

        // ---- S = Q @ K^T  (128x64, warp does 16x64)
        float s[8][4];
#pragma unroll
        for (int ni = 0; ni < 8; ++ni)
#pragma unroll
            for (int r = 0; r < 4; ++r) s[ni][r] = 0.f;

#pragma unroll
        for (int ks = 0; ks < 16; ++ks) {
            int cc = ks * 8 + qc;
#pragma unroll
            for (int ni = 0; ni < 8; ++ni) {
                uint32_t bf[2] = { Ks[(ni * 8 + qr) * AT_KLD + cc],
                                   Ks[(ni * 8 + qr) * AT_KLD + cc + 4] };
                mma16n8k8(s[ni], qf[ks], bf);
            }
        }

        // ---- scale + causal mask + online softmax
        const bool domask = (kt * 64 + 63 > qbase_w);
#pragma unroll
        for (int r = 0; r < 2; ++r) {
            int qg = qbase_w + qr + 8 * r;
            float mx = -1e30f;
#pragma unroll
            for (int ni = 0; ni < 8; ++ni) {
#pragma unroll
                for (int v = 0; v < 2; ++v) {
                    float val = s[ni][r * 2 + v] * scl;
                    if (domask) {
                        int kg = kt * 64 + ni * 8 + 2 * qc + v;
                        if (kg > qg) val = -1e30f;
                    }
                    s[ni][r * 2 + v] = val;
                    mx = fmaxf(mx, val);
                }
            }
            mx = fmaxf(mx, __shfl_xor_sync(0xffffffffu, mx, 1));
            mx = fmaxf(mx, __shfl_xor_sync(0xffffffffu, mx, 2));
            float mnew  = fmaxf(m[r], mx);
            float alpha = __expf(m[r] - mnew);
            float sum = 0.f;
#pragma unroll
            for (int ni = 0; ni < 8; ++ni) {
                float p0 = __expf(s[ni][r * 2]     - mnew);
                float p1 = __expf(s[ni][r * 2 + 1] - mnew);
                sum += p0 + p1;
                *(uint2*)&Pw[(qr + 8 * r) * AT_PLD + ni * 8 + 2 * qc] =
                    make_uint2(f2tf32(p0), f2tf32(p1));
            }
            sum += __shfl_xor_sync(0xffffffffu, sum, 1);
            sum += __shfl_xor_sync(0xffffffffu, sum, 2);
            l[r] = l[r] * alpha + sum;
            m[r] = mnew;
#pragma unroll
            for (int dt = 0; dt < 16; ++dt) {
                O[dt][r * 2]     *= alpha;
                O[dt][r * 2 + 1] *= alpha;
            }
        }
        __syncwarp();

        // ---- O += P @ V   (warp: 16x128, k=64)
#pragma unroll
        for (int kk = 0; kk < 8; ++kk) {
            int c = kk * 8 + qc;
            uint32_t af[4] = { Pw[qr * AT_PLD + c],       Pw[(qr + 8) * AT_PLD + c],
                               Pw[qr * AT_PLD + c + 4],   Pw[(qr + 8) * AT_PLD + c + 4] };
#pragma unroll
            for (int dt = 0; dt < 16; ++dt) {
                uint32_t bf[2] = { Vs[c * AT_VLD + dt * 8 + qr],
                                   Vs[(c + 4) * AT_VLD + dt * 8 + qr] };
                mma16n8k8(O[dt], af, bf);
            }
        }

        __syncthreads();
        if (kt + 2 < nkt) load_kv(kt + 2);
        cp_commit();
    }

    // ---- finalize, write y
#pragma unroll
    for (int r = 0; r < 2; ++r) {
        float inv = 1.0f / l[r];
        int row = qbase_w + qr + 8 * r;
        float* yp = y + (size_t)(b * SEQ + row) * C_DIM + h * HD;
#pragma unroll
        for (int dt = 0; dt < 16; ++dt)
            *(float2*)&yp[dt * 8 + 2 * qc] =
                make_float2(O[dt][r * 2] * inv, O[dt][r * 2 + 1] * inv);
    }
}

// ---------------------------------------------------------------------------
extern "C" void kernel_launch(void* const* d_in, const int* in_sizes, int n_in,
                              void* d_out, int out_size)
{
    const float* x    = (const float*)d_in[0];
    const float* Wqkv = (const float*)d_in[1];
    const float* Wout = (const float*)d_in[2];
    float* out = (float*)d_out;

    float *qkv = nullptr, *y = nullptr, *wqkvT = nullptr, *woutT = nullptr;
    cudaGetSymbolAddress((void**)&qkv,   g_qkv);
    cudaGetSymbolAddress((void**)&y,     g_y);
    cudaGetSymbolAddress((void**)&wqkvT, g_WqkvT);
    cudaGetSymbolAddress((void**)&woutT, g_WoutT);

    static bool attr_set = false;
    if (!attr_set) {
        cudaFuncSetAttribute(tc_gemm_kernel, cudaFuncAttributeMaxDynamicSharedMemorySize, GM_SMEM_BYTES);
        cudaFuncSetAttribute(attn_kernel,    cudaFuncAttributeMaxDynamicSharedMemorySize, AT_SMEM_BYTES);
        attr_set = true;
    }

    // 0) transpose weights to K-major (B^T) layout
    transpose_kernel<<<dim3(QKV_N / 32, C_DIM / 32), dim3(32, 8)>>>(Wqkv, wqkvT, C_DIM, QKV_N);
    transpose_kernel<<<dim3(C_DIM / 32, C_DIM / 32), dim3(32, 8)>>>(Wout, woutT, C_DIM, C_DIM);

    // 1) qkv = x @ Wqkv  (tf32 mma.sync; outputs pre-rounded to tf32)
    tc_gemm_kernel<<<dim3(QKV_N / GM_BN, MROWS / GM_BM), 256, GM_SMEM_BYTES>>>(
        x, wqkvT, qkv, MROWS, QKV_N, C_DIM, 1);

    // 2) RoPE in-place on q,k (tf32-rounded outputs)
    rope_kernel<<<(MROWS * 2 * NH * 8) / 256, 256>>>(qkv);

    // 3) causal flash attention (tensor cores) -> y [B,T,C]
    attn_kernel<<<dim3(SEQ / 128, NB * NH), 256, AT_SMEM_BYTES>>>(qkv, y);

    // 4) out = y @ Wout  (tf32 mma.sync; full fp32 output)
    tc_gemm_kernel<<<dim3(C_DIM / GM_BN, MROWS / GM_BM), 256, GM_SMEM_BYTES>>>(
        y, woutT, out, MROWS, C_DIM, C_DIM, 0);
}

// round 7
// speedup vs baseline: 5.2968x; 1.7100x over previous
#include <cuda_runtime.h>
#include <cuda_fp16.h>
#include <math.h>
#include <stdint.h>

// Problem constants
constexpr int C_DIM   = 2048;
constexpr int NH      = 16;
constexpr int HD      = 128;
constexpr int SEQ     = 512;
constexpr int NB      = 16;
constexpr int MROWS   = NB * SEQ;        // 8192
constexpr int QKV_N   = 3 * C_DIM;       // 6144

// Scratch (static device globals — no runtime allocation)
__device__ __half g_xh    [(long long)MROWS * C_DIM];   // 32 MiB
__device__ __half g_qkvh  [(long long)MROWS * QKV_N];   // 96 MiB
__device__ __half g_vT    [(long long)MROWS * C_DIM];   // 32 MiB  [b][h][d][t]
__device__ __half g_yh    [(long long)MROWS * C_DIM];   // 32 MiB
__device__ __half g_WqkvTh[(long long)QKV_N * C_DIM];   // 24 MiB
__device__ __half g_WoutTh[(long long)C_DIM * C_DIM];   //  8 MiB

// ---------------------------------------------------------------------------
// helpers
// ---------------------------------------------------------------------------
__device__ __forceinline__ uint32_t smem_u32(const void* p) {
    return (uint32_t)__cvta_generic_to_shared(p);
}
__device__ __forceinline__ void cp_async16(uint32_t dst, const void* src) {
    asm volatile("cp.async.cg.shared.global [%0], [%1], 16;\n"
                 :: "r"(dst), "l"(src) : "memory");
}
__device__ __forceinline__ void cp_commit() {
    asm volatile("cp.async.commit_group;\n" ::: "memory");
}
template <int N>
__device__ __forceinline__ void cp_wait_group() {
    asm volatile("cp.async.wait_group %0;\n" :: "n"(N) : "memory");
}
// m16n8k16 f16 MMA, fp32 accumulate
__device__ __forceinline__ void mma_f16(float* c, const uint32_t* a, const uint32_t* b) {
    asm volatile(
        "mma.sync.aligned.m16n8k16.row.col.f32.f16.f16.f32 "
        "{%0,%1,%2,%3}, {%4,%5,%6,%7}, {%8,%9}, {%0,%1,%2,%3};"
        : "+f"(c[0]), "+f"(c[1]), "+f"(c[2]), "+f"(c[3])
        : "r"(a[0]), "r"(a[1]), "r"(a[2]), "r"(a[3]), "r"(b[0]), "r"(b[1]));
}
__device__ __forceinline__ uint32_t pack_h2(float lo, float hi) {
    __half2 h = __floats2half2_rn(lo, hi);
    return *(uint32_t*)&h;
}

// ---------------------------------------------------------------------------
// fp32 -> fp16 bulk convert (vectorized x4)
// ---------------------------------------------------------------------------
__global__ __launch_bounds__(256) void f2h_kernel(
    const float* __restrict__ in, __half* __restrict__ out)
{
    int i = (blockIdx.x * 256 + threadIdx.x) * 4;
    float4 v = *(const float4*)(in + i);
    *(__half2*)(out + i)     = __floats2half2_rn(v.x, v.y);
    *(__half2*)(out + i + 2) = __floats2half2_rn(v.z, v.w);
}

// ---------------------------------------------------------------------------
// Tiled transpose + fp16 convert: out[c][r] = (half)in[r][c].
// ---------------------------------------------------------------------------
__global__ __launch_bounds__(256) void transpose_h_kernel(
    const float* __restrict__ in, __half* __restrict__ out, int R, int Ccols)
{
    __shared__ float t[32][33];
    int c0 = blockIdx.x * 32, r0 = blockIdx.y * 32;
    int x = c0 + threadIdx.x;
#pragma unroll
    for (int i = threadIdx.y; i < 32; i += 8)
        t[i][threadIdx.x] = in[(size_t)(r0 + i) * Ccols + x];
    __syncthreads();
    int ox = r0 + threadIdx.x;
#pragma unroll
    for (int i = threadIdx.y; i < 32; i += 8)
        out[(size_t)(c0 + i) * R + ox] = __float2half_rn(t[threadIdx.x][i]);
}

// ---------------------------------------------------------------------------
// Batched V transpose: vT[b][h][d][t] = qkv[b*T+t][2C + h*HD + d]  (fp16)
// ---------------------------------------------------------------------------
__global__ __launch_bounds__(256) void vtrans_kernel(
    const __half* __restrict__ qkv, __half* __restrict__ vT)
{
    __shared__ __half t[32][33];
    int bh = blockIdx.z;
    int b = bh >> 4, h = bh & 15;
    int d0 = blockIdx.x * 32, t0 = blockIdx.y * 32;
    const __half* src = qkv + (size_t)b * SEQ * QKV_N + 2 * C_DIM + h * HD;
#pragma unroll
    for (int i = threadIdx.y; i < 32; i += 8)
        t[i][threadIdx.x] = src[(size_t)(t0 + i) * QKV_N + d0 + threadIdx.x];
    __syncthreads();
    __half* dst = vT + (size_t)bh * HD * SEQ;
#pragma unroll
    for (int i = threadIdx.y; i < 32; i += 8)
        dst[(size_t)(d0 + i) * SEQ + t0 + threadIdx.x] = t[threadIdx.x][i];
}

// ---------------------------------------------------------------------------
// RoPE in-place on fp16 qkv (fp32 math)
// ---------------------------------------------------------------------------
__global__ __launch_bounds__(256) void rope_h_kernel(__half* __restrict__ qkv)
{
    int idx = blockIdx.x * blockDim.x + threadIdx.x;
    int d = idx & 7;
    int h = (idx >> 3) & 15;
    int w = (idx >> 7) & 1;
    int m = idx >> 8;
    int t = m & (SEQ - 1);

    size_t base = (size_t)m * QKV_N + w * C_DIM + h * HD;
    float inv = powf(10000.0f, -(float)d * 0.125f);
    float ang = (float)t * inv;
    float s, c;
    sincosf(ang, &s, &c);
    float x1 = __half2float(qkv[base + d]);
    float x2 = __half2float(qkv[base + d + 8]);
    qkv[base + d]     = __float2half_rn(x1 * c - x2 * s);
    qkv[base + d + 8] = __float2half_rn(x2 * c + x1 * s);
}

// ---------------------------------------------------------------------------
// fp16 tensor-core GEMM:  C[M,N] = A[M,K] @ Bt[N,K]^T,  fp32 accumulate.
// CTA 128x256, BK=32, 8 warps (2x4), warp tile 64x64, 3-stage cp.async.
// Smem pitch 40 halves -> all fragment LDS32 bank-conflict-free.
// ---------------------------------------------------------------------------
constexpr int HG_BM = 128, HG_BN = 256, HG_BK = 32, HG_NST = 3;
constexpr int HG_AP = 40;                    // halves per smem row
constexpr int HG_AT = 128 * HG_AP;           // 5120 halves
constexpr int HG_BT = 256 * HG_AP;           // 10240 halves
constexpr int HG_ST = HG_AT + HG_BT;         // 15360 halves / stage
constexpr int HG_SMEM_BYTES = HG_NST * HG_ST * 2;   // 92160

template <typename OutT>
__global__ __launch_bounds__(256, 1) void hgemm_kernel(
    const __half* __restrict__ A, const __half* __restrict__ Bt,
    OutT* __restrict__ C, int M, int N, int K)
{
    extern __shared__ __half smh[];
    const uint32_t sb = smem_u32(smh);

    const int tid  = threadIdx.x;
    const int warp = tid >> 5;
    const int lane = tid & 31;
    const int qr   = lane >> 2;
    const int qc   = lane & 3;
    const int m0   = blockIdx.y * HG_BM;
    const int n0   = blockIdx.x * HG_BN;
    const int wm   = (warp >> 2) * 64;
    const int wn   = (warp & 3) * 64;

    float acc[4][8][4];
#pragma unroll
    for (int mi = 0; mi < 4; ++mi)
#pragma unroll
        for (int ni = 0; ni < 8; ++ni)
#pragma unroll
            for (int r = 0; r < 4; ++r) acc[mi][ni][r] = 0.f;

    const int NITER = K / HG_BK;

    auto load_stage = [&](int ki) {
        const int k0  = ki * HG_BK;
        const int buf = ki % HG_NST;
        const uint32_t sa  = sb + (uint32_t)buf * HG_ST * 2;
        const uint32_t sbb = sa + HG_AT * 2;
#pragma unroll
        for (int it = 0; it < 2; ++it) {
            int idx = it * 256 + tid;
            int r = idx >> 2, c8 = idx & 3;
            cp_async16(sa + (uint32_t)(r * HG_AP + c8 * 8) * 2,
                       A + (size_t)(m0 + r) * K + k0 + c8 * 8);
        }
#pragma unroll
        for (int it = 0; it < 4; ++it) {
            int idx = it * 256 + tid;
            int r = idx >> 2, c8 = idx & 3;
            cp_async16(sbb + (uint32_t)(r * HG_AP + c8 * 8) * 2,
                       Bt + (size_t)(n0 + r) * K + k0 + c8 * 8);
        }
    };

    load_stage(0); cp_commit();
    load_stage(1); cp_commit();

    for (int i = 0; i < NITER; ++i) {
        cp_wait_group<1>();
        __syncthreads();

        if (i + 2 < NITER) load_stage(i + 2);
        cp_commit();

        const uint32_t* As = (const uint32_t*)(smh + (size_t)(i % HG_NST) * HG_ST);
        const uint32_t* Bs = As + HG_AT / 2;

#pragma unroll
        for (int ks = 0; ks < 2; ++ks) {
            const int u = ks * 8 + qc;        // u32 offset within row (pitch 20)
            uint32_t af[4][4], bf[8][2];
#pragma unroll
            for (int mi = 0; mi < 4; ++mi) {
                int r = wm + mi * 16 + qr;
                af[mi][0] = As[r * 20 + u];
                af[mi][1] = As[(r + 8) * 20 + u];
                af[mi][2] = As[r * 20 + u + 4];
                af[mi][3] = As[(r + 8) * 20 + u + 4];
            }
#pragma unroll
            for (int ni = 0; ni < 8; ++ni) {
                int n = wn + ni * 8 + qr;
                bf[ni][0] = Bs[n * 20 + u];
                bf[ni][1] = Bs[n * 20 + u + 4];
            }
#pragma unroll
            for (int mi = 0; mi < 4; ++mi)
#pragma unroll
                for (int ni = 0; ni < 8; ++ni)
                    mma_f16(acc[mi][ni], af[mi], bf[ni]);
        }
        __syncthreads();
    }

    // epilogue
#pragma unroll
    for (int mi = 0; mi < 4; ++mi) {
#pragma unroll
        for (int ni = 0; ni < 8; ++ni) {
            int row = m0 + wm + mi * 16 + qr;
            int col = n0 + wn + ni * 8 + 2 * qc;
            if constexpr (sizeof(OutT) == 2) {
                *(__half2*)&C[(size_t)row * N + col] =
                    __floats2half2_rn(acc[mi][ni][0], acc[mi][ni][1]);
                *(__half2*)&C[(size_t)(row + 8) * N + col] =
                    __floats2half2_rn(acc[mi][ni][2], acc[mi][ni][3]);
            } else {
                *(float2*)&C[(size_t)row * N + col] =
                    make_float2(acc[mi][ni][0], acc[mi][ni][1]);
                *(float2*)&C[(size_t)(row + 8) * N + col] =
                    make_float2(acc[mi][ni][2], acc[mi][ni][3]);
            }
        }
    }
}

// ---------------------------------------------------------------------------
// fp16 tensor-core flash attention (causal).
// CTA: 128 q-rows of one (b,h); 8 warps x 16 q-rows. Q frags in registers.
// K row-major [seq][d]; V transposed [d][seq]; P per-warp smem bounce.
// All pitches chosen bank-conflict-free for LDS32 fragment loads.
// ---------------------------------------------------------------------------
constexpr int AH_KP  = 136;                       // K/Q pitch (halves)
constexpr int AH_VP  = 72;                        // Vt pitch
constexpr int AH_PP  = 72;                        // P pitch
constexpr int AH_K0  = 0;                         // 64 x 136
constexpr int AH_K1  = AH_K0 + 64 * AH_KP;        // 8704
constexpr int AH_V0  = AH_K1 + 64 * AH_KP;        // 17408 (128 x 72)
constexpr int AH_V1  = AH_V0 + 128 * AH_VP;       // 26624
constexpr int AH_P   = AH_V1 + 128 * AH_VP;       // 35840 (+ warp*16*72)
constexpr int AH_SMEM_HALVES = AH_P + 8 * 16 * AH_PP;   // 45056
constexpr int AH_SMEM_BYTES  = AH_SMEM_HALVES * 2;      // 90112

__global__ __launch_bounds__(256, 1) void attn_kernel(
    const __half* __restrict__ qkv, const __half* __restrict__ vT,
    __half* __restrict__ y)
{
    extern __shared__ __half smh[];
    const uint32_t sb = smem_u32(smh);
    const int tid  = threadIdx.x;
    const int warp = tid >> 5;
    const int lane = tid & 31;
    const int qr   = lane >> 2;
    const int qc   = lane & 3;
    const int qt   = blockIdx.x;            // 128-row q tile, 0..3
    const int bh   = blockIdx.y;
    const int b = bh >> 4, h = bh & 15;

    const __half* baseQ = qkv + (size_t)b * SEQ * QKV_N + h * HD;
    const __half* baseK = baseQ + C_DIM;
    const __half* vbase = vT + (size_t)bh * HD * SEQ;
    const int q0 = qt * 128;

    // ---- stage Q (128 x 128 halves) into K0/K1 region, pitch 136
#pragma unroll
    for (int it = 0; it < 8; ++it) {
        int idx = it * 256 + tid;
        int r = idx >> 4, c8 = idx & 15;
        cp_async16(sb + (uint32_t)(r * AH_KP + c8 * 8) * 2,
                   baseQ + (size_t)(q0 + r) * QKV_N + c8 * 8);
    }
    cp_commit(); cp_wait_group<0>(); __syncthreads();

    // extract Q fragments (8 k-steps of 16)
    uint32_t qf[8][4];
    {
        const uint32_t* Qs = (const uint32_t*)smh + (size_t)warp * 16 * (AH_KP / 2);
#pragma unroll
        for (int ks = 0; ks < 8; ++ks) {
            int u = ks * 8 + qc;
            qf[ks][0] = Qs[qr * 68 + u];
            qf[ks][1] = Qs[(qr + 8) * 68 + u];
            qf[ks][2] = Qs[qr * 68 + u + 4];
            qf[ks][3] = Qs[(qr + 8) * 68 + u + 4];
        }
    }
    __syncthreads();

    float O[16][4];
#pragma unroll
    for (int dt = 0; dt < 16; ++dt)
#pragma unroll
        for (int r = 0; r < 4; ++r) O[dt][r] = 0.f;
    float m[2] = {-1e30f, -1e30f}, l[2] = {0.f, 0.f};

    const int nkt = 2 * qt + 2;

    auto load_kv = [&](int kt) {
        int buf = kt & 1;
        int t0  = kt * 64;
        const uint32_t kb = sb + (uint32_t)(buf ? AH_K1 : AH_K0) * 2;
        const uint32_t vb = sb + (uint32_t)(buf ? AH_V1 : AH_V0) * 2;
#pragma unroll
        for (int it = 0; it < 4; ++it) {
            int idx = it * 256 + tid;
            int r = idx >> 4, c8 = idx & 15;
            cp_async16(kb + (uint32_t)(r * AH_KP + c8 * 8) * 2,
                       baseK + (size_t)(t0 + r) * QKV_N + c8 * 8);
        }
#pragma unroll
        for (int it = 0; it < 4; ++it) {
            int idx = it * 256 + tid;
            int r = idx >> 3, c8 = idx & 7;
            cp_async16(vb + (uint32_t)(r * AH_VP + c8 * 8) * 2,
                       vbase + (size_t)r * SEQ + t0 + c8 * 8);
        }
    };

    load_kv(0); cp_commit();
    load_kv(1); cp_commit();

    const int qbase_w = q0 + warp * 16;
    uint32_t* Pw = (uint32_t*)(smh + AH_P) + (size_t)warp * 16 * (AH_PP / 2);
    const float scl = 0.08838834764831845f;   // 1/sqrt(128)

    for (int kt = 0; kt < nkt; ++kt) {
        cp_wait_group<1>();
        __syncthreads();
        const uint32_t* Ks = (const uint32_t*)(smh + ((kt & 1) ? AH_K1 : AH_K0));
        const uint32_t* Vs = (const uint32_t*)(smh + ((kt & 1) ? AH_V1 : AH_V0));

        // ---- S = Q @ K^T  (warp: 16 x 64)
        float s[8][4];
#pragma unroll
        for (int ni = 0; ni < 8; ++ni)
#pragma unroll
            for (int r = 0; r < 4; ++r) s[ni][r] = 0.f;

#pragma unroll
        for (int ks = 0; ks < 8; ++ks) {
            int u = ks * 8 + qc;
#pragma unroll
            for (int ni = 0; ni < 8; ++ni) {
                const uint32_t* Kr = Ks + (ni * 8 + qr) * 68;
                uint32_t bf[2] = { Kr[u], Kr[u + 4] };
                mma_f16(s[ni], qf[ks], bf);
            }
        }

        // ---- scale + causal mask + online softmax, write P (fp16)
        const bool domask = (kt * 64 + 63 > qbase_w);
#pragma unroll
        for (int r = 0; r < 2; ++r) {
            int qg = qbase_w + qr + 8 * r;
            float mx = -1e30f;
#pragma unroll
            for (int ni = 0; ni < 8; ++ni) {
#pragma unroll
                for (int v = 0; v < 2; ++v) {
                    float val = s[ni][r * 2 + v] * scl;
                    if (domask) {
                        int kg = kt * 64 + ni * 8 + 2 * qc + v;
                        if (kg > qg) val = -1e30f;
                    }
                    s[ni][r * 2 + v] = val;
                    mx = fmaxf(mx, val);
                }
            }
            mx = fmaxf(mx, __shfl_xor_sync(0xffffffffu, mx, 1));
            mx = fmaxf(mx, __shfl_xor_sync(0xffffffffu, mx, 2));
            float mnew  = fmaxf(m[r], mx);
            float alpha = __expf(m[r] - mnew);
            float sum = 0.f;
#pragma unroll
            for (int ni = 0; ni < 8; ++ni) {
                float p0 = __expf(s[ni][r * 2]     - mnew);
                float p1 = __expf(s[ni][r * 2 + 1] - mnew);
                sum += p0 + p1;
                Pw[(qr + 8 * r) * 36 + ni * 4 + qc] = pack_h2(p0, p1);
            }
            sum += __shfl_xor_sync(0xffffffffu, sum, 1);
            sum += __shfl_xor_sync(0xffffffffu, sum, 2);
            l[r] = l[r] * alpha + sum;
            m[r] = mnew;
#pragma unroll
            for (int dt = 0; dt < 16; ++dt) {
                O[dt][r * 2]     *= alpha;
                O[dt][r * 2 + 1] *= alpha;
            }
        }
        __syncwarp();

        // ---- O += P @ V   (warp: 16 x 128, k = 64)
#pragma unroll
        for (int kk = 0; kk < 4; ++kk) {
            int u = kk * 8 + qc;
            uint32_t af[4] = { Pw[qr * 36 + u],     Pw[(qr + 8) * 36 + u],
                               Pw[qr * 36 + u + 4], Pw[(qr + 8) * 36 + u + 4] };
#pragma unroll
            for (int dt = 0; dt < 16; ++dt) {
                const uint32_t* Vr = Vs + (dt * 8 + qr) * 36;
                uint32_t bf[2] = { Vr[u], Vr[u + 4] };
                mma_f16(O[dt], af, bf);
            }
        }

        __syncthreads();
        if (kt + 2 < nkt) load_kv(kt + 2);
        cp_commit();
    }

    // ---- finalize, write y (fp16)
#pragma unroll
    for (int r = 0; r < 2; ++r) {
        float inv = 1.0f / l[r];
        int row = qbase_w + qr + 8 * r;
        __half* yp = y + (size_t)(b * SEQ + row) * C_DIM + h * HD;
#pragma unroll
        for (int dt = 0; dt < 16; ++dt)
            *(__half2*)&yp[dt * 8 + 2 * qc] =
                __floats2half2_rn(O[dt][r * 2] * inv, O[dt][r * 2 + 1] * inv);
    }
}

// ---------------------------------------------------------------------------
extern "C" void kernel_launch(void* const* d_in, const int* in_sizes, int n_in,
                              void* d_out, int out_size)
{
    const float* x    = (const float*)d_in[0];
    const float* Wqkv = (const float*)d_in[1];
    const float* Wout = (const float*)d_in[2];
    float* out = (float*)d_out;

    __half *xh, *qkvh, *vt, *yh, *wqkvTh, *woutTh;
    cudaGetSymbolAddress((void**)&xh,     g_xh);
    cudaGetSymbolAddress((void**)&qkvh,   g_qkvh);
    cudaGetSymbolAddress((void**)&vt,     g_vT);
    cudaGetSymbolAddress((void**)&yh,     g_yh);
    cudaGetSymbolAddress((void**)&wqkvTh, g_WqkvTh);
    cudaGetSymbolAddress((void**)&woutTh, g_WoutTh);

    static bool attr_set = false;
    if (!attr_set) {
        cudaFuncSetAttribute(hgemm_kernel<__half>, cudaFuncAttributeMaxDynamicSharedMemorySize, HG_SMEM_BYTES);
        cudaFuncSetAttribute(hgemm_kernel<float>,  cudaFuncAttributeMaxDynamicSharedMemorySize, HG_SMEM_BYTES);
        cudaFuncSetAttribute(attn_kernel,          cudaFuncAttributeMaxDynamicSharedMemorySize, AH_SMEM_BYTES);
        attr_set = true;
    }

    // 0) convert x -> fp16; transpose+convert weights -> [N,K] fp16
    f2h_kernel<<<(MROWS * C_DIM / 4) / 256, 256>>>(x, xh);
    transpose_h_kernel<<<dim3(QKV_N / 32, C_DIM / 32), dim3(32, 8)>>>(Wqkv, wqkvTh, C_DIM, QKV_N);
    transpose_h_kernel<<<dim3(C_DIM / 32, C_DIM / 32), dim3(32, 8)>>>(Wout, woutTh, C_DIM, C_DIM);

    // 1) qkv = x @ Wqkv  (fp16 MMA, fp16 out)
    hgemm_kernel<__half><<<dim3(QKV_N / HG_BN, MROWS / HG_BM), 256, HG_SMEM_BYTES>>>(
        xh, wqkvTh, qkvh, MROWS, QKV_N, C_DIM);

    // 2) RoPE in-place on q,k (fp16)
    rope_h_kernel<<<(MROWS * 2 * NH * 8) / 256, 256>>>(qkvh);

    // 3) V transpose for PV operand layout
    vtrans_kernel<<<dim3(HD / 32, SEQ / 32, NB * NH), dim3(32, 8)>>>(qkvh, vt);

    // 4) causal flash attention (fp16 MMA) -> y fp16
    attn_kernel<<<dim3(SEQ / 128, NB * NH), 256, AH_SMEM_BYTES>>>(qkvh, vt, yh);

    // 5) out = y @ Wout  (fp16 MMA, fp32 out)
    hgemm_kernel<float><<<dim3(C_DIM / HG_BN, MROWS / HG_BM), 256, HG_SMEM_BYTES>>>(
        yh, woutTh, out, MROWS, C_DIM, C_DIM);
}

// round 8
// speedup vs baseline: 5.5925x; 1.0558x over previous
#include <cuda_runtime.h>
#include <cuda_fp16.h>
#include <math.h>
#include <stdint.h>

// Problem constants
constexpr int C_DIM   = 2048;
constexpr int NH      = 16;
constexpr int HD      = 128;
constexpr int SEQ     = 512;
constexpr int NB      = 16;
constexpr int MROWS   = NB * SEQ;        // 8192
constexpr int QKV_N   = 3 * C_DIM;       // 6144

// Scratch (static device globals — no runtime allocation)
__device__ __half g_xh    [(long long)MROWS * C_DIM];   // 32 MiB
__device__ __half g_qkvh  [(long long)MROWS * QKV_N];   // 96 MiB
__device__ __half g_yh    [(long long)MROWS * C_DIM];   // 32 MiB
__device__ __half g_WqkvTh[(long long)QKV_N * C_DIM];   // 24 MiB
__device__ __half g_WoutTh[(long long)C_DIM * C_DIM];   //  8 MiB

// ---------------------------------------------------------------------------
// helpers
// ---------------------------------------------------------------------------
__device__ __forceinline__ uint32_t smem_u32(const void* p) {
    return (uint32_t)__cvta_generic_to_shared(p);
}
__device__ __forceinline__ void cp_async16(uint32_t dst, const void* src) {
    asm volatile("cp.async.cg.shared.global [%0], [%1], 16;\n"
                 :: "r"(dst), "l"(src) : "memory");
}
__device__ __forceinline__ void cp_commit() {
    asm volatile("cp.async.commit_group;\n" ::: "memory");
}
template <int N>
__device__ __forceinline__ void cp_wait_group() {
    asm volatile("cp.async.wait_group %0;\n" :: "n"(N) : "memory");
}
__device__ __forceinline__ void mma_f16(float* c, const uint32_t* a, const uint32_t* b) {
    asm volatile(
        "mma.sync.aligned.m16n8k16.row.col.f32.f16.f16.f32 "
        "{%0,%1,%2,%3}, {%4,%5,%6,%7}, {%8,%9}, {%0,%1,%2,%3};"
        : "+f"(c[0]), "+f"(c[1]), "+f"(c[2]), "+f"(c[3])
        : "r"(a[0]), "r"(a[1]), "r"(a[2]), "r"(a[3]), "r"(b[0]), "r"(b[1]));
}
__device__ __forceinline__ void ldsm_x4(uint32_t* r, uint32_t addr) {
    asm volatile("ldmatrix.sync.aligned.m8n8.x4.shared.b16 {%0,%1,%2,%3}, [%4];"
                 : "=r"(r[0]), "=r"(r[1]), "=r"(r[2]), "=r"(r[3]) : "r"(addr));
}
__device__ __forceinline__ void ldsm_x4_t(uint32_t* r, uint32_t addr) {
    asm volatile("ldmatrix.sync.aligned.m8n8.x4.trans.shared.b16 {%0,%1,%2,%3}, [%4];"
                 : "=r"(r[0]), "=r"(r[1]), "=r"(r[2]), "=r"(r[3]) : "r"(addr));
}
__device__ __forceinline__ uint32_t pack_h2(float lo, float hi) {
    __half2 h = __floats2half2_rn(lo, hi);
    return *(uint32_t*)&h;
}

// ---------------------------------------------------------------------------
// fp32 -> fp16 bulk convert
// ---------------------------------------------------------------------------
__global__ __launch_bounds__(256) void f2h_kernel(
    const float* __restrict__ in, __half* __restrict__ out)
{
    int i = (blockIdx.x * 256 + threadIdx.x) * 4;
    float4 v = *(const float4*)(in + i);
    *(__half2*)(out + i)     = __floats2half2_rn(v.x, v.y);
    *(__half2*)(out + i + 2) = __floats2half2_rn(v.z, v.w);
}

// ---------------------------------------------------------------------------
// Tiled transpose + fp16 convert: out[c][r] = (half)in[r][c].
// ---------------------------------------------------------------------------
__global__ __launch_bounds__(256) void transpose_h_kernel(
    const float* __restrict__ in, __half* __restrict__ out, int R, int Ccols)
{
    __shared__ float t[32][33];
    int c0 = blockIdx.x * 32, r0 = blockIdx.y * 32;
    int x = c0 + threadIdx.x;
#pragma unroll
    for (int i = threadIdx.y; i < 32; i += 8)
        t[i][threadIdx.x] = in[(size_t)(r0 + i) * Ccols + x];
    __syncthreads();
    int ox = r0 + threadIdx.x;
#pragma unroll
    for (int i = threadIdx.y; i < 32; i += 8)
        out[(size_t)(c0 + i) * R + ox] = __float2half_rn(t[threadIdx.x][i]);
}

// ---------------------------------------------------------------------------
// RoPE in-place on fp16 qkv (fp32 math)
// ---------------------------------------------------------------------------
__global__ __launch_bounds__(256) void rope_h_kernel(__half* __restrict__ qkv)
{
    int idx = blockIdx.x * blockDim.x + threadIdx.x;
    int d = idx & 7;
    int h = (idx >> 3) & 15;
    int w = (idx >> 7) & 1;
    int m = idx >> 8;
    int t = m & (SEQ - 1);

    size_t base = (size_t)m * QKV_N + w * C_DIM + h * HD;
    float inv = powf(10000.0f, -(float)d * 0.125f);
    float ang = (float)t * inv;
    float s, c;
    sincosf(ang, &s, &c);
    float x1 = __half2float(qkv[base + d]);
    float x2 = __half2float(qkv[base + d + 8]);
    qkv[base + d]     = __float2half_rn(x1 * c - x2 * s);
    qkv[base + d + 8] = __float2half_rn(x2 * c + x1 * s);
}

// ---------------------------------------------------------------------------
// fp16 tensor-core GEMM with ldmatrix:  C[M,N] = A[M,K] @ Bt[N,K]^T
// CTA 128x256, BK=32, 8 warps (2x4), warp tile 64x64, 3-stage cp.async.
// ---------------------------------------------------------------------------
constexpr int HG_BM = 128, HG_BN = 256, HG_BK = 32, HG_NST = 3;
constexpr int HG_AP = 40;                    // halves per smem row
constexpr int HG_AT = 128 * HG_AP;           // 5120 halves
constexpr int HG_BT = 256 * HG_AP;           // 10240 halves
constexpr int HG_ST = HG_AT + HG_BT;         // 15360 halves / stage
constexpr int HG_SMEM_BYTES = HG_NST * HG_ST * 2;   // 92160

template <typename OutT>
__global__ __launch_bounds__(256, 1) void hgemm_kernel(
    const __half* __restrict__ A, const __half* __restrict__ Bt,
    OutT* __restrict__ C, int M, int N, int K)
{
    extern __shared__ __half smh[];
    const uint32_t sb = smem_u32(smh);

    const int tid  = threadIdx.x;
    const int warp = tid >> 5;
    const int lane = tid & 31;
    const int qr   = lane >> 2;
    const int qc   = lane & 3;
    const int m0   = blockIdx.y * HG_BM;
    const int n0   = blockIdx.x * HG_BN;
    const int wm   = (warp >> 2) * 64;
    const int wn   = (warp & 3) * 64;

    // ldmatrix lane offsets (in halves)
    const uint32_t aoff = (uint32_t)(((lane & 7) + ((lane >> 3) & 1) * 8) * HG_AP + (lane >> 4) * 8);
    const uint32_t boff = (uint32_t)(((lane & 7) + (lane >> 4) * 8) * HG_AP + ((lane >> 3) & 1) * 8);

    float acc[4][8][4];
#pragma unroll
    for (int mi = 0; mi < 4; ++mi)
#pragma unroll
        for (int ni = 0; ni < 8; ++ni)
#pragma unroll
            for (int r = 0; r < 4; ++r) acc[mi][ni][r] = 0.f;

    const int NITER = K / HG_BK;

    auto load_stage = [&](int ki) {
        const int k0  = ki * HG_BK;
        const int buf = ki % HG_NST;
        const uint32_t sa  = sb + (uint32_t)buf * HG_ST * 2;
        const uint32_t sbb = sa + HG_AT * 2;
#pragma unroll
        for (int it = 0; it < 2; ++it) {
            int idx = it * 256 + tid;
            int r = idx >> 2, c8 = idx & 3;
            cp_async16(sa + (uint32_t)(r * HG_AP + c8 * 8) * 2,
                       A + (size_t)(m0 + r) * K + k0 + c8 * 8);
        }
#pragma unroll
        for (int it = 0; it < 4; ++it) {
            int idx = it * 256 + tid;
            int r = idx >> 2, c8 = idx & 3;
            cp_async16(sbb + (uint32_t)(r * HG_AP + c8 * 8) * 2,
                       Bt + (size_t)(n0 + r) * K + k0 + c8 * 8);
        }
    };

    load_stage(0); cp_commit();
    load_stage(1); cp_commit();

    for (int i = 0; i < NITER; ++i) {
        cp_wait_group<1>();
        __syncthreads();

        if (i + 2 < NITER) load_stage(i + 2);
        cp_commit();

        const uint32_t sa  = sb + (uint32_t)(i % HG_NST) * HG_ST * 2;
        const uint32_t sbb = sa + HG_AT * 2;

#pragma unroll
        for (int ks = 0; ks < 2; ++ks) {
            uint32_t af[4][4], bf[4][4];
#pragma unroll
            for (int mi = 0; mi < 4; ++mi)
                ldsm_x4(af[mi], sa + (uint32_t)((wm + mi * 16) * HG_AP + ks * 16) * 2 + aoff * 2);
#pragma unroll
            for (int np = 0; np < 4; ++np)
                ldsm_x4(bf[np], sbb + (uint32_t)((wn + np * 16) * HG_AP + ks * 16) * 2 + boff * 2);
#pragma unroll
            for (int mi = 0; mi < 4; ++mi)
#pragma unroll
                for (int np = 0; np < 4; ++np) {
                    mma_f16(acc[mi][np * 2],     af[mi], &bf[np][0]);
                    mma_f16(acc[mi][np * 2 + 1], af[mi], &bf[np][2]);
                }
        }
        __syncthreads();
    }

    // epilogue
#pragma unroll
    for (int mi = 0; mi < 4; ++mi) {
#pragma unroll
        for (int ni = 0; ni < 8; ++ni) {
            int row = m0 + wm + mi * 16 + qr;
            int col = n0 + wn + ni * 8 + 2 * qc;
            if constexpr (sizeof(OutT) == 2) {
                *(__half2*)&C[(size_t)row * N + col] =
                    __floats2half2_rn(acc[mi][ni][0], acc[mi][ni][1]);
                *(__half2*)&C[(size_t)(row + 8) * N + col] =
                    __floats2half2_rn(acc[mi][ni][2], acc[mi][ni][3]);
            } else {
                *(float2*)&C[(size_t)row * N + col] =
                    make_float2(acc[mi][ni][0], acc[mi][ni][1]);
                *(float2*)&C[(size_t)(row + 8) * N + col] =
                    make_float2(acc[mi][ni][2], acc[mi][ni][3]);
            }
        }
    }
}

// ---------------------------------------------------------------------------
// fp16 flash attention (causal) with ldmatrix + register-resident P.
// CTA: 128 q-rows of one (b,h); 8 warps x 16 q-rows.
// K and V both row-major [64][136] in smem, double-buffered.
// S accumulator frags repacked directly as PV A-operand (no smem bounce).
// V B-operand via ldmatrix.trans (no V transpose kernel).
// ---------------------------------------------------------------------------
constexpr int AH_KP  = 136;                       // pitch (halves)
constexpr int AH_K0  = 0;
constexpr int AH_K1  = AH_K0 + 64 * AH_KP;        // 8704
constexpr int AH_V0  = AH_K1 + 64 * AH_KP;        // 17408
constexpr int AH_V1  = AH_V0 + 64 * AH_KP;        // 26112
constexpr int AH_SMEM_HALVES = AH_V1 + 64 * AH_KP;   // 34816
constexpr int AH_SMEM_BYTES  = AH_SMEM_HALVES * 2;   // 69632

__global__ __launch_bounds__(256, 1) void attn_kernel(
    const __half* __restrict__ qkv, __half* __restrict__ y)
{
    extern __shared__ __half smh[];
    const uint32_t sb = smem_u32(smh);
    const int tid  = threadIdx.x;
    const int warp = tid >> 5;
    const int lane = tid & 31;
    const int qr   = lane >> 2;
    const int qc   = lane & 3;
    const int qt   = blockIdx.x;            // 128-row q tile, 0..3
    const int bh   = blockIdx.y;
    const int b = bh >> 4, h = bh & 15;

    const __half* baseQ = qkv + (size_t)b * SEQ * QKV_N + h * HD;
    const __half* baseK = baseQ + C_DIM;
    const __half* baseV = baseQ + 2 * C_DIM;
    const int q0 = qt * 128;

    // ldmatrix lane offsets (halves), pitch AH_KP
    const uint32_t aoff = (uint32_t)(((lane & 7) + ((lane >> 3) & 1) * 8) * AH_KP + (lane >> 4) * 8);
    const uint32_t koff = (uint32_t)(((lane & 7) + (lane >> 4) * 8) * AH_KP + ((lane >> 3) & 1) * 8);
    const uint32_t voff = aoff;   // trans V uses the A-style address pattern

    // ---- stage Q (128 x 128 halves) into V0+V1 region
#pragma unroll
    for (int it = 0; it < 8; ++it) {
        int idx = it * 256 + tid;
        int r = idx >> 4, c8 = idx & 15;
        cp_async16(sb + (uint32_t)(AH_V0 + r * AH_KP + c8 * 8) * 2,
                   baseQ + (size_t)(q0 + r) * QKV_N + c8 * 8);
    }
    cp_commit(); cp_wait_group<0>(); __syncthreads();

    // Q fragments via ldmatrix (8 k-steps of 16 over d)
    uint32_t qf[8][4];
    {
        const uint32_t qbase = sb + (uint32_t)(AH_V0 + warp * 16 * AH_KP) * 2 + aoff * 2;
#pragma unroll
        for (int ks = 0; ks < 8; ++ks)
            ldsm_x4(qf[ks], qbase + (uint32_t)(ks * 16) * 2);
    }
    __syncthreads();

    float O[16][4];
#pragma unroll
    for (int dt = 0; dt < 16; ++dt)
#pragma unroll
        for (int r = 0; r < 4; ++r) O[dt][r] = 0.f;
    float m[2] = {-1e30f, -1e30f}, l[2] = {0.f, 0.f};

    const int nkt = 2 * qt + 2;

    auto load_kv = [&](int kt) {
        int buf = kt & 1;
        int t0  = kt * 64;
        const uint32_t kb = sb + (uint32_t)(buf ? AH_K1 : AH_K0) * 2;
        const uint32_t vb = sb + (uint32_t)(buf ? AH_V1 : AH_V0) * 2;
#pragma unroll
        for (int it = 0; it < 4; ++it) {
            int idx = it * 256 + tid;
            int r = idx >> 4, c8 = idx & 15;
            cp_async16(kb + (uint32_t)(r * AH_KP + c8 * 8) * 2,
                       baseK + (size_t)(t0 + r) * QKV_N + c8 * 8);
        }
#pragma unroll
        for (int it = 0; it < 4; ++it) {
            int idx = it * 256 + tid;
            int r = idx >> 4, c8 = idx & 15;
            cp_async16(vb + (uint32_t)(r * AH_KP + c8 * 8) * 2,
                       baseV + (size_t)(t0 + r) * QKV_N + c8 * 8);
        }
    };

    load_kv(0); cp_commit();
    load_kv(1); cp_commit();

    const int qbase_w = q0 + warp * 16;
    const float scl = 0.08838834764831845f;   // 1/sqrt(128)

    for (int kt = 0; kt < nkt; ++kt) {
        cp_wait_group<1>();
        __syncthreads();
        const uint32_t kb = sb + (uint32_t)((kt & 1) ? AH_K1 : AH_K0) * 2;
        const uint32_t vb = sb + (uint32_t)((kt & 1) ? AH_V1 : AH_V0) * 2;

        // ---- S = Q @ K^T  (warp: 16 x 64)
        float s[8][4];
#pragma unroll
        for (int ni = 0; ni < 8; ++ni)
#pragma unroll
            for (int r = 0; r < 4; ++r) s[ni][r] = 0.f;

#pragma unroll
        for (int ks = 0; ks < 8; ++ks) {
#pragma unroll
            for (int np = 0; np < 4; ++np) {
                uint32_t bf[4];
                ldsm_x4(bf, kb + (uint32_t)(np * 16 * AH_KP + ks * 16) * 2 + koff * 2);
                mma_f16(s[np * 2],     qf[ks], &bf[0]);
                mma_f16(s[np * 2 + 1], qf[ks], &bf[2]);
            }
        }

        // ---- scale + causal mask + online softmax (P stays in registers)
        const bool domask = (kt * 64 + 63 > qbase_w);
#pragma unroll
        for (int r = 0; r < 2; ++r) {
            int qg = qbase_w + qr + 8 * r;
            float mx = -1e30f;
#pragma unroll
            for (int ni = 0; ni < 8; ++ni) {
#pragma unroll
                for (int v = 0; v < 2; ++v) {
                    float val = s[ni][r * 2 + v] * scl;
                    if (domask) {
                        int kg = kt * 64 + ni * 8 + 2 * qc + v;
                        if (kg > qg) val = -1e30f;
                    }
                    s[ni][r * 2 + v] = val;
                    mx = fmaxf(mx, val);
                }
            }
            mx = fmaxf(mx, __shfl_xor_sync(0xffffffffu, mx, 1));
            mx = fmaxf(mx, __shfl_xor_sync(0xffffffffu, mx, 2));
            float mnew  = fmaxf(m[r], mx);
            float alpha = __expf(m[r] - mnew);
            float sum = 0.f;
#pragma unroll
            for (int ni = 0; ni < 8; ++ni) {
                float p0 = __expf(s[ni][r * 2]     - mnew);
                float p1 = __expf(s[ni][r * 2 + 1] - mnew);
                sum += p0 + p1;
                s[ni][r * 2]     = p0;
                s[ni][r * 2 + 1] = p1;
            }
            sum += __shfl_xor_sync(0xffffffffu, sum, 1);
            sum += __shfl_xor_sync(0xffffffffu, sum, 2);
            l[r] = l[r] * alpha + sum;
            m[r] = mnew;
#pragma unroll
            for (int dt = 0; dt < 16; ++dt) {
                O[dt][r * 2]     *= alpha;
                O[dt][r * 2 + 1] *= alpha;
            }
        }

        // ---- O += P @ V  (P from accumulator frags; V via ldmatrix.trans)
#pragma unroll
        for (int kk = 0; kk < 4; ++kk) {
            uint32_t af[4] = {
                pack_h2(s[2 * kk][0],     s[2 * kk][1]),
                pack_h2(s[2 * kk][2],     s[2 * kk][3]),
                pack_h2(s[2 * kk + 1][0], s[2 * kk + 1][1]),
                pack_h2(s[2 * kk + 1][2], s[2 * kk + 1][3]) };
#pragma unroll
            for (int dp = 0; dp < 8; ++dp) {
                uint32_t bf[4];
                ldsm_x4_t(bf, vb + (uint32_t)(kk * 16 * AH_KP + dp * 16) * 2 + voff * 2);
                mma_f16(O[dp * 2],     af, &bf[0]);
                mma_f16(O[dp * 2 + 1], af, &bf[2]);
            }
        }

        __syncthreads();
        if (kt + 2 < nkt) load_kv(kt + 2);
        cp_commit();
    }

    // ---- finalize, write y (fp16)
#pragma unroll
    for (int r = 0; r < 2; ++r) {
        float inv = 1.0f / l[r];
        int row = qbase_w + qr + 8 * r;
        __half* yp = y + (size_t)(b * SEQ + row) * C_DIM + h * HD;
#pragma unroll
        for (int dt = 0; dt < 16; ++dt)
            *(__half2*)&yp[dt * 8 + 2 * qc] =
                __floats2half2_rn(O[dt][r * 2] * inv, O[dt][r * 2 + 1] * inv);
    }
}

// ---------------------------------------------------------------------------
extern "C" void kernel_launch(void* const* d_in, const int* in_sizes, int n_in,
                              void* d_out, int out_size)
{
    const float* x    = (const float*)d_in[0];
    const float* Wqkv = (const float*)d_in[1];
    const float* Wout = (const float*)d_in[2];
    float* out = (float*)d_out;

    __half *xh, *qkvh, *yh, *wqkvTh, *woutTh;
    cudaGetSymbolAddress((void**)&xh,     g_xh);
    cudaGetSymbolAddress((void**)&qkvh,   g_qkvh);
    cudaGetSymbolAddress((void**)&yh,     g_yh);
    cudaGetSymbolAddress((void**)&wqkvTh, g_WqkvTh);
    cudaGetSymbolAddress((void**)&woutTh, g_WoutTh);

    static bool attr_set = false;
    if (!attr_set) {
        cudaFuncSetAttribute(hgemm_kernel<__half>, cudaFuncAttributeMaxDynamicSharedMemorySize, HG_SMEM_BYTES);
        cudaFuncSetAttribute(hgemm_kernel<float>,  cudaFuncAttributeMaxDynamicSharedMemorySize, HG_SMEM_BYTES);
        cudaFuncSetAttribute(attn_kernel,          cudaFuncAttributeMaxDynamicSharedMemorySize, AH_SMEM_BYTES);
        attr_set = true;
    }

    // 0) convert x -> fp16; transpose+convert weights -> [N,K] fp16
    f2h_kernel<<<(MROWS * C_DIM / 4) / 256, 256>>>(x, xh);
    transpose_h_kernel<<<dim3(QKV_N / 32, C_DIM / 32), dim3(32, 8)>>>(Wqkv, wqkvTh, C_DIM, QKV_N);
    transpose_h_kernel<<<dim3(C_DIM / 32, C_DIM / 32), dim3(32, 8)>>>(Wout, woutTh, C_DIM, C_DIM);

    // 1) qkv = x @ Wqkv  (fp16 MMA + ldmatrix)
    hgemm_kernel<__half><<<dim3(QKV_N / HG_BN, MROWS / HG_BM), 256, HG_SMEM_BYTES>>>(
        xh, wqkvTh, qkvh, MROWS, QKV_N, C_DIM);

    // 2) RoPE in-place on q,k (fp16)
    rope_h_kernel<<<(MROWS * 2 * NH * 8) / 256, 256>>>(qkvh);

    // 3) causal flash attention (fp16 MMA + ldmatrix, register P) -> y fp16
    attn_kernel<<<dim3(SEQ / 128, NB * NH), 256, AH_SMEM_BYTES>>>(qkvh, yh);

    // 4) out = y @ Wout  (fp16 MMA + ldmatrix, fp32 out)
    hgemm_kernel<float><<<dim3(C_DIM / HG_BN, MROWS / HG_BM), 256, HG_SMEM_BYTES>>>(
        yh, woutTh, out, MROWS, C_DIM, C_DIM);
}

// round 9
// speedup vs baseline: 6.7568x; 1.2082x over previous
#include <cuda_runtime.h>
#include <cuda_fp16.h>
#include <math.h>
#include <stdint.h>

// Problem constants
constexpr int C_DIM   = 2048;
constexpr int NH      = 16;
constexpr int HD      = 128;
constexpr int SEQ     = 512;
constexpr int NB      = 16;
constexpr int MROWS   = NB * SEQ;        // 8192
constexpr int QKV_N   = 3 * C_DIM;       // 6144

// Scratch (static device globals — no runtime allocation)
__device__ __half g_xh    [(long long)MROWS * C_DIM];   // 32 MiB
__device__ __half g_qkvh  [(long long)MROWS * QKV_N];   // 96 MiB
__device__ __half g_yh    [(long long)MROWS * C_DIM];   // 32 MiB
__device__ __half g_WqkvTh[(long long)QKV_N * C_DIM];   // 24 MiB
__device__ __half g_WoutTh[(long long)C_DIM * C_DIM];   //  8 MiB

// ---------------------------------------------------------------------------
// helpers
// ---------------------------------------------------------------------------
__device__ __forceinline__ uint32_t smem_u32(const void* p) {
    return (uint32_t)__cvta_generic_to_shared(p);
}
__device__ __forceinline__ void cp_async16(uint32_t dst, const void* src) {
    asm volatile("cp.async.cg.shared.global [%0], [%1], 16;\n"
                 :: "r"(dst), "l"(src) : "memory");
}
__device__ __forceinline__ void cp_commit() {
    asm volatile("cp.async.commit_group;\n" ::: "memory");
}
template <int N>
__device__ __forceinline__ void cp_wait_group() {
    asm volatile("cp.async.wait_group %0;\n" :: "n"(N) : "memory");
}
__device__ __forceinline__ void mma_f16(float* c, const uint32_t* a, const uint32_t* b) {
    asm volatile(
        "mma.sync.aligned.m16n8k16.row.col.f32.f16.f16.f32 "
        "{%0,%1,%2,%3}, {%4,%5,%6,%7}, {%8,%9}, {%0,%1,%2,%3};"
        : "+f"(c[0]), "+f"(c[1]), "+f"(c[2]), "+f"(c[3])
        : "r"(a[0]), "r"(a[1]), "r"(a[2]), "r"(a[3]), "r"(b[0]), "r"(b[1]));
}
__device__ __forceinline__ void ldsm_x4(uint32_t* r, uint32_t addr) {
    asm volatile("ldmatrix.sync.aligned.m8n8.x4.shared.b16 {%0,%1,%2,%3}, [%4];"
                 : "=r"(r[0]), "=r"(r[1]), "=r"(r[2]), "=r"(r[3]) : "r"(addr));
}
__device__ __forceinline__ void ldsm_x4_t(uint32_t* r, uint32_t addr) {
    asm volatile("ldmatrix.sync.aligned.m8n8.x4.trans.shared.b16 {%0,%1,%2,%3}, [%4];"
                 : "=r"(r[0]), "=r"(r[1]), "=r"(r[2]), "=r"(r[3]) : "r"(addr));
}
__device__ __forceinline__ uint32_t pack_h2(float lo, float hi) {
    __half2 h = __floats2half2_rn(lo, hi);
    return *(uint32_t*)&h;
}

// ---------------------------------------------------------------------------
// fp32 -> fp16 bulk convert
// ---------------------------------------------------------------------------
__global__ __launch_bounds__(256) void f2h_kernel(
    const float* __restrict__ in, __half* __restrict__ out)
{
    int i = (blockIdx.x * 256 + threadIdx.x) * 4;
    float4 v = *(const float4*)(in + i);
    *(__half2*)(out + i)     = __floats2half2_rn(v.x, v.y);
    *(__half2*)(out + i + 2) = __floats2half2_rn(v.z, v.w);
}

// ---------------------------------------------------------------------------
// Tiled transpose + fp16 convert: out[c][r] = (half)in[r][c].
// ---------------------------------------------------------------------------
__global__ __launch_bounds__(256) void transpose_h_kernel(
    const float* __restrict__ in, __half* __restrict__ out, int R, int Ccols)
{
    __shared__ float t[32][33];
    int c0 = blockIdx.x * 32, r0 = blockIdx.y * 32;
    int x = c0 + threadIdx.x;
#pragma unroll
    for (int i = threadIdx.y; i < 32; i += 8)
        t[i][threadIdx.x] = in[(size_t)(r0 + i) * Ccols + x];
    __syncthreads();
    int ox = r0 + threadIdx.x;
#pragma unroll
    for (int i = threadIdx.y; i < 32; i += 8)
        out[(size_t)(c0 + i) * R + ox] = __float2half_rn(t[threadIdx.x][i]);
}

// ---------------------------------------------------------------------------
// RoPE in-place on fp16 qkv (fp32 math)
// ---------------------------------------------------------------------------
__global__ __launch_bounds__(256) void rope_h_kernel(__half* __restrict__ qkv)
{
    int idx = blockIdx.x * blockDim.x + threadIdx.x;
    int d = idx & 7;
    int h = (idx >> 3) & 15;
    int w = (idx >> 7) & 1;
    int m = idx >> 8;
    int t = m & (SEQ - 1);

    size_t base = (size_t)m * QKV_N + w * C_DIM + h * HD;
    float inv = powf(10000.0f, -(float)d * 0.125f);
    float ang = (float)t * inv;
    float s, c;
    sincosf(ang, &s, &c);
    float x1 = __half2float(qkv[base + d]);
    float x2 = __half2float(qkv[base + d + 8]);
    qkv[base + d]     = __float2half_rn(x1 * c - x2 * s);
    qkv[base + d + 8] = __float2half_rn(x2 * c + x1 * s);
}

// ---------------------------------------------------------------------------
// fp16 tensor-core GEMM with ldmatrix:  C[M,N] = A[M,K] @ Bt[N,K]^T
// CTA 128x128, BK=32, 8 warps (2x4), warp tile 64x32, 3-stage cp.async.
// __launch_bounds__(256,2): cap regs at 128 -> 2 CTAs/SM (latency hiding).
// ---------------------------------------------------------------------------
constexpr int HG_BM = 128, HG_BN = 128, HG_BK = 32, HG_NST = 3;
constexpr int HG_AP = 40;                    // halves per smem row
constexpr int HG_AT = 128 * HG_AP;           // 5120 halves (A tile)
constexpr int HG_BT = 128 * HG_AP;           // 5120 halves (B tile)
constexpr int HG_ST = HG_AT + HG_BT;         // 10240 halves / stage
constexpr int HG_SMEM_BYTES = HG_NST * HG_ST * 2;   // 61440

template <typename OutT>
__global__ __launch_bounds__(256, 2) void hgemm_kernel(
    const __half* __restrict__ A, const __half* __restrict__ Bt,
    OutT* __restrict__ C, int M, int N, int K)
{
    extern __shared__ __half smh[];
    const uint32_t sb = smem_u32(smh);

    const int tid  = threadIdx.x;
    const int warp = tid >> 5;
    const int lane = tid & 31;
    const int qr   = lane >> 2;
    const int qc   = lane & 3;
    const int m0   = blockIdx.y * HG_BM;
    const int n0   = blockIdx.x * HG_BN;
    const int wm   = (warp >> 2) * 64;
    const int wn   = (warp & 3) * 32;

    // ldmatrix lane offsets (in halves)
    const uint32_t aoff = (uint32_t)(((lane & 7) + ((lane >> 3) & 1) * 8) * HG_AP + (lane >> 4) * 8);
    const uint32_t boff = (uint32_t)(((lane & 7) + (lane >> 4) * 8) * HG_AP + ((lane >> 3) & 1) * 8);

    float acc[4][4][4];
#pragma unroll
    for (int mi = 0; mi < 4; ++mi)
#pragma unroll
        for (int ni = 0; ni < 4; ++ni)
#pragma unroll
            for (int r = 0; r < 4; ++r) acc[mi][ni][r] = 0.f;

    const int NITER = K / HG_BK;

    auto load_stage = [&](int ki) {
        const int k0  = ki * HG_BK;
        const int buf = ki % HG_NST;
        const uint32_t sa  = sb + (uint32_t)buf * HG_ST * 2;
        const uint32_t sbb = sa + HG_AT * 2;
#pragma unroll
        for (int it = 0; it < 2; ++it) {
            int idx = it * 256 + tid;
            int r = idx >> 2, c8 = idx & 3;
            cp_async16(sa + (uint32_t)(r * HG_AP + c8 * 8) * 2,
                       A + (size_t)(m0 + r) * K + k0 + c8 * 8);
        }
#pragma unroll
        for (int it = 0; it < 2; ++it) {
            int idx = it * 256 + tid;
            int r = idx >> 2, c8 = idx & 3;
            cp_async16(sbb + (uint32_t)(r * HG_AP + c8 * 8) * 2,
                       Bt + (size_t)(n0 + r) * K + k0 + c8 * 8);
        }
    };

    load_stage(0); cp_commit();
    load_stage(1); cp_commit();

    for (int i = 0; i < NITER; ++i) {
        cp_wait_group<1>();
        __syncthreads();

        if (i + 2 < NITER) load_stage(i + 2);
        cp_commit();

        const uint32_t sa  = sb + (uint32_t)(i % HG_NST) * HG_ST * 2;
        const uint32_t sbb = sa + HG_AT * 2;

#pragma unroll
        for (int ks = 0; ks < 2; ++ks) {
            uint32_t af[4][4], bf[2][4];
#pragma unroll
            for (int mi = 0; mi < 4; ++mi)
                ldsm_x4(af[mi], sa + (uint32_t)((wm + mi * 16) * HG_AP + ks * 16) * 2 + aoff * 2);
#pragma unroll
            for (int np = 0; np < 2; ++np)
                ldsm_x4(bf[np], sbb + (uint32_t)((wn + np * 16) * HG_AP + ks * 16) * 2 + boff * 2);
#pragma unroll
            for (int mi = 0; mi < 4; ++mi)
#pragma unroll
                for (int np = 0; np < 2; ++np) {
                    mma_f16(acc[mi][np * 2],     af[mi], &bf[np][0]);
                    mma_f16(acc[mi][np * 2 + 1], af[mi], &bf[np][2]);
                }
        }
        __syncthreads();
    }

    // epilogue
#pragma unroll
    for (int mi = 0; mi < 4; ++mi) {
#pragma unroll
        for (int ni = 0; ni < 4; ++ni) {
            int row = m0 + wm + mi * 16 + qr;
            int col = n0 + wn + ni * 8 + 2 * qc;
            if constexpr (sizeof(OutT) == 2) {
                *(__half2*)&C[(size_t)row * N + col] =
                    __floats2half2_rn(acc[mi][ni][0], acc[mi][ni][1]);
                *(__half2*)&C[(size_t)(row + 8) * N + col] =
                    __floats2half2_rn(acc[mi][ni][2], acc[mi][ni][3]);
            } else {
                *(float2*)&C[(size_t)row * N + col] =
                    make_float2(acc[mi][ni][0], acc[mi][ni][1]);
                *(float2*)&C[(size_t)(row + 8) * N + col] =
                    make_float2(acc[mi][ni][2], acc[mi][ni][3]);
            }
        }
    }
}

// ---------------------------------------------------------------------------
// fp16 flash attention (causal) with ldmatrix + register-resident P.
// CTA: 128 q-rows of one (b,h); 8 warps x 16 q-rows.
// K and V both row-major [64][136] in smem, double-buffered.
// ---------------------------------------------------------------------------
constexpr int AH_KP  = 136;                       // pitch (halves)
constexpr int AH_K0  = 0;
constexpr int AH_K1  = AH_K0 + 64 * AH_KP;        // 8704
constexpr int AH_V0  = AH_K1 + 64 * AH_KP;        // 17408
constexpr int AH_V1  = AH_V0 + 64 * AH_KP;        // 26112
constexpr int AH_SMEM_HALVES = AH_V1 + 64 * AH_KP;   // 34816
constexpr int AH_SMEM_BYTES  = AH_SMEM_HALVES * 2;   // 69632

__global__ __launch_bounds__(256, 1) void attn_kernel(
    const __half* __restrict__ qkv, __half* __restrict__ y)
{
    extern __shared__ __half smh[];
    const uint32_t sb = smem_u32(smh);
    const int tid  = threadIdx.x;
    const int warp = tid >> 5;
    const int lane = tid & 31;
    const int qr   = lane >> 2;
    const int qc   = lane & 3;
    const int qt   = blockIdx.x;            // 128-row q tile, 0..3
    const int bh   = blockIdx.y;
    const int b = bh >> 4, h = bh & 15;

    const __half* baseQ = qkv + (size_t)b * SEQ * QKV_N + h * HD;
    const __half* baseK = baseQ + C_DIM;
    const __half* baseV = baseQ + 2 * C_DIM;
    const int q0 = qt * 128;

    // ldmatrix lane offsets (halves), pitch AH_KP
    const uint32_t aoff = (uint32_t)(((lane & 7) + ((lane >> 3) & 1) * 8) * AH_KP + (lane >> 4) * 8);
    const uint32_t koff = (uint32_t)(((lane & 7) + (lane >> 4) * 8) * AH_KP + ((lane >> 3) & 1) * 8);
    const uint32_t voff = aoff;   // trans V uses the A-style address pattern

    // ---- stage Q (128 x 128 halves) into V0+V1 region
#pragma unroll
    for (int it = 0; it < 8; ++it) {
        int idx = it * 256 + tid;
        int r = idx >> 4, c8 = idx & 15;
        cp_async16(sb + (uint32_t)(AH_V0 + r * AH_KP + c8 * 8) * 2,
                   baseQ + (size_t)(q0 + r) * QKV_N + c8 * 8);
    }
    cp_commit(); cp_wait_group<0>(); __syncthreads();

    // Q fragments via ldmatrix (8 k-steps of 16 over d)
    uint32_t qf[8][4];
    {
        const uint32_t qbase = sb + (uint32_t)(AH_V0 + warp * 16 * AH_KP) * 2 + aoff * 2;
#pragma unroll
        for (int ks = 0; ks < 8; ++ks)
            ldsm_x4(qf[ks], qbase + (uint32_t)(ks * 16) * 2);
    }
    __syncthreads();

    float O[16][4];
#pragma unroll
    for (int dt = 0; dt < 16; ++dt)
#pragma unroll
        for (int r = 0; r < 4; ++r) O[dt][r] = 0.f;
    float m[2] = {-1e30f, -1e30f}, l[2] = {0.f, 0.f};

    const int nkt = 2 * qt + 2;

    auto load_kv = [&](int kt) {
        int buf = kt & 1;
        int t0  = kt * 64;
        const uint32_t kb = sb + (uint32_t)(buf ? AH_K1 : AH_K0) * 2;
        const uint32_t vb = sb + (uint32_t)(buf ? AH_V1 : AH_V0) * 2;
#pragma unroll
        for (int it = 0; it < 4; ++it) {
            int idx = it * 256 + tid;
            int r = idx >> 4, c8 = idx & 15;
            cp_async16(kb + (uint32_t)(r * AH_KP + c8 * 8) * 2,
                       baseK + (size_t)(t0 + r) * QKV_N + c8 * 8);
        }
#pragma unroll
        for (int it = 0; it < 4; ++it) {
            int idx = it * 256 + tid;
            int r = idx >> 4, c8 = idx & 15;
            cp_async16(vb + (uint32_t)(r * AH_KP + c8 * 8) * 2,
                       baseV + (size_t)(t0 + r) * QKV_N + c8 * 8);
        }
    };

    load_kv(0); cp_commit();
    load_kv(1); cp_commit();

    const int qbase_w = q0 + warp * 16;
    const float scl = 0.08838834764831845f;   // 1/sqrt(128)

    for (int kt = 0; kt < nkt; ++kt) {
        cp_wait_group<1>();
        __syncthreads();
        const uint32_t kb = sb + (uint32_t)((kt & 1) ? AH_K1 : AH_K0) * 2;
        const uint32_t vb = sb + (uint32_t)((kt & 1) ? AH_V1 : AH_V0) * 2;

        // ---- S = Q @ K^T  (warp: 16 x 64)
        float s[8][4];
#pragma unroll
        for (int ni = 0; ni < 8; ++ni)
#pragma unroll
            for (int r = 0; r < 4; ++r) s[ni][r] = 0.f;

#pragma unroll
        for (int ks = 0; ks < 8; ++ks) {
#pragma unroll
            for (int np = 0; np < 4; ++np) {
                uint32_t bf[4];
                ldsm_x4(bf, kb + (uint32_t)(np * 16 * AH_KP + ks * 16) * 2 + koff * 2);
                mma_f16(s[np * 2],     qf[ks], &bf[0]);
                mma_f16(s[np * 2 + 1], qf[ks], &bf[2]);
            }
        }

        // ---- scale + causal mask + online softmax (P stays in registers)
        const bool domask = (kt * 64 + 63 > qbase_w);
#pragma unroll
        for (int r = 0; r < 2; ++r) {
            int qg = qbase_w + qr + 8 * r;
            float mx = -1e30f;
#pragma unroll
            for (int ni = 0; ni < 8; ++ni) {
#pragma unroll
                for (int v = 0; v < 2; ++v) {
                    float val = s[ni][r * 2 + v] * scl;
                    if (domask) {
                        int kg = kt * 64 + ni * 8 + 2 * qc + v;
                        if (kg > qg) val = -1e30f;
                    }
                    s[ni][r * 2 + v] = val;
                    mx = fmaxf(mx, val);
                }
            }
            mx = fmaxf(mx, __shfl_xor_sync(0xffffffffu, mx, 1));
            mx = fmaxf(mx, __shfl_xor_sync(0xffffffffu, mx, 2));
            float mnew  = fmaxf(m[r], mx);
            float alpha = __expf(m[r] - mnew);
            float sum = 0.f;
#pragma unroll
            for (int ni = 0; ni < 8; ++ni) {
                float p0 = __expf(s[ni][r * 2]     - mnew);
                float p1 = __expf(s[ni][r * 2 + 1] - mnew);
                sum += p0 + p1;
                s[ni][r * 2]     = p0;
                s[ni][r * 2 + 1] = p1;
            }
            sum += __shfl_xor_sync(0xffffffffu, sum, 1);
            sum += __shfl_xor_sync(0xffffffffu, sum, 2);
            l[r] = l[r] * alpha + sum;
            m[r] = mnew;
#pragma unroll
            for (int dt = 0; dt < 16; ++dt) {
                O[dt][r * 2]     *= alpha;
                O[dt][r * 2 + 1] *= alpha;
            }
        }

        // ---- O += P @ V  (P from accumulator frags; V via ldmatrix.trans)
#pragma unroll
        for (int kk = 0; kk < 4; ++kk) {
            uint32_t af[4] = {
                pack_h2(s[2 * kk][0],     s[2 * kk][1]),
                pack_h2(s[2 * kk][2],     s[2 * kk][3]),
                pack_h2(s[2 * kk + 1][0], s[2 * kk + 1][1]),
                pack_h2(s[2 * kk + 1][2], s[2 * kk + 1][3]) };
#pragma unroll
            for (int dp = 0; dp < 8; ++dp) {
                uint32_t bf[4];
                ldsm_x4_t(bf, vb + (uint32_t)(kk * 16 * AH_KP + dp * 16) * 2 + voff * 2);
                mma_f16(O[dp * 2],     af, &bf[0]);
                mma_f16(O[dp * 2 + 1], af, &bf[2]);
            }
        }

        __syncthreads();
        if (kt + 2 < nkt) load_kv(kt + 2);
        cp_commit();
    }

    // ---- finalize, write y (fp16)
#pragma unroll
    for (int r = 0; r < 2; ++r) {
        float inv = 1.0f / l[r];
        int row = qbase_w + qr + 8 * r;
        __half* yp = y + (size_t)(b * SEQ + row) * C_DIM + h * HD;
#pragma unroll
        for (int dt = 0; dt < 16; ++dt)
            *(__half2*)&yp[dt * 8 + 2 * qc] =
                __floats2half2_rn(O[dt][r * 2] * inv, O[dt][r * 2 + 1] * inv);
    }
}

// ---------------------------------------------------------------------------
extern "C" void kernel_launch(void* const* d_in, const int* in_sizes, int n_in,
                              void* d_out, int out_size)
{
    const float* x    = (const float*)d_in[0];
    const float* Wqkv = (const float*)d_in[1];
    const float* Wout = (const float*)d_in[2];
    float* out = (float*)d_out;

    __half *xh, *qkvh, *yh, *wqkvTh, *woutTh;
    cudaGetSymbolAddress((void**)&xh,     g_xh);
    cudaGetSymbolAddress((void**)&qkvh,   g_qkvh);
    cudaGetSymbolAddress((void**)&yh,     g_yh);
    cudaGetSymbolAddress((void**)&wqkvTh, g_WqkvTh);
    cudaGetSymbolAddress((void**)&woutTh, g_WoutTh);

    static bool attr_set = false;
    if (!attr_set) {
        cudaFuncSetAttribute(hgemm_kernel<__half>, cudaFuncAttributeMaxDynamicSharedMemorySize, HG_SMEM_BYTES);
        cudaFuncSetAttribute(hgemm_kernel<float>,  cudaFuncAttributeMaxDynamicSharedMemorySize, HG_SMEM_BYTES);
        cudaFuncSetAttribute(attn_kernel,          cudaFuncAttributeMaxDynamicSharedMemorySize, AH_SMEM_BYTES);
        attr_set = true;
    }

    // 0) convert x -> fp16; transpose+convert weights -> [N,K] fp16
    f2h_kernel<<<(MROWS * C_DIM / 4) / 256, 256>>>(x, xh);
    transpose_h_kernel<<<dim3(QKV_N / 32, C_DIM / 32), dim3(32, 8)>>>(Wqkv, wqkvTh, C_DIM, QKV_N);
    transpose_h_kernel<<<dim3(C_DIM / 32, C_DIM / 32), dim3(32, 8)>>>(Wout, woutTh, C_DIM, C_DIM);

    // 1) qkv = x @ Wqkv  (fp16 MMA + ldmatrix, 2 CTAs/SM)
    hgemm_kernel<__half><<<dim3(QKV_N / HG_BN, MROWS / HG_BM), 256, HG_SMEM_BYTES>>>(
        xh, wqkvTh, qkvh, MROWS, QKV_N, C_DIM);

    // 2) RoPE in-place on q,k (fp16)
    rope_h_kernel<<<(MROWS * 2 * NH * 8) / 256, 256>>>(qkvh);

    // 3) causal flash attention (fp16 MMA + ldmatrix, register P) -> y fp16
    attn_kernel<<<dim3(SEQ / 128, NB * NH), 256, AH_SMEM_BYTES>>>(qkvh, yh);

    // 4) out = y @ Wout  (fp16 MMA + ldmatrix, fp32 out)
    hgemm_kernel<float><<<dim3(C_DIM / HG_BN, MROWS / HG_BM), 256, HG_SMEM_BYTES>>>(
        yh, woutTh, out, MROWS, C_DIM, C_DIM);
}

// round 10
// speedup vs baseline: 7.0842x; 1.0485x over previous
#include <cuda_runtime.h>
#include <cuda_fp16.h>
#include <math.h>
#include <stdint.h>

// Problem constants
constexpr int C_DIM   = 2048;
constexpr int NH      = 16;
constexpr int HD      = 128;
constexpr int SEQ     = 512;
constexpr int NB      = 16;
constexpr int MROWS   = NB * SEQ;        // 8192
constexpr int QKV_N   = 3 * C_DIM;       // 6144

// Scratch (static device globals — no runtime allocation)
__device__ __half g_xh    [(long long)MROWS * C_DIM];   // 32 MiB
__device__ __half g_qkvh  [(long long)MROWS * QKV_N];   // 96 MiB
__device__ __half g_yh    [(long long)MROWS * C_DIM];   // 32 MiB
__device__ __half g_WqkvTh[(long long)QKV_N * C_DIM];   // 24 MiB
__device__ __half g_WoutTh[(long long)C_DIM * C_DIM];   //  8 MiB

// ---------------------------------------------------------------------------
// helpers
// ---------------------------------------------------------------------------
__device__ __forceinline__ uint32_t smem_u32(const void* p) {
    return (uint32_t)__cvta_generic_to_shared(p);
}
__device__ __forceinline__ void cp_async16(uint32_t dst, const void* src) {
    asm volatile("cp.async.cg.shared.global [%0], [%1], 16;\n"
                 :: "r"(dst), "l"(src) : "memory");
}
__device__ __forceinline__ void cp_commit() {
    asm volatile("cp.async.commit_group;\n" ::: "memory");
}
template <int N>
__device__ __forceinline__ void cp_wait_group() {
    asm volatile("cp.async.wait_group %0;\n" :: "n"(N) : "memory");
}
__device__ __forceinline__ void mma_f16(float* c, const uint32_t* a, const uint32_t* b) {
    asm volatile(
        "mma.sync.aligned.m16n8k16.row.col.f32.f16.f16.f32 "
        "{%0,%1,%2,%3}, {%4,%5,%6,%7}, {%8,%9}, {%0,%1,%2,%3};"
        : "+f"(c[0]), "+f"(c[1]), "+f"(c[2]), "+f"(c[3])
        : "r"(a[0]), "r"(a[1]), "r"(a[2]), "r"(a[3]), "r"(b[0]), "r"(b[1]));
}
__device__ __forceinline__ void ldsm_x4(uint32_t* r, uint32_t addr) {
    asm volatile("ldmatrix.sync.aligned.m8n8.x4.shared.b16 {%0,%1,%2,%3}, [%4];"
                 : "=r"(r[0]), "=r"(r[1]), "=r"(r[2]), "=r"(r[3]) : "r"(addr));
}
__device__ __forceinline__ void ldsm_x4_t(uint32_t* r, uint32_t addr) {
    asm volatile("ldmatrix.sync.aligned.m8n8.x4.trans.shared.b16 {%0,%1,%2,%3}, [%4];"
                 : "=r"(r[0]), "=r"(r[1]), "=r"(r[2]), "=r"(r[3]) : "r"(addr));
}
__device__ __forceinline__ uint32_t pack_h2(float lo, float hi) {
    __half2 h = __floats2half2_rn(lo, hi);
    return *(uint32_t*)&h;
}

// ---------------------------------------------------------------------------
// fp32 -> fp16 bulk convert
// ---------------------------------------------------------------------------
__global__ __launch_bounds__(256) void f2h_kernel(
    const float* __restrict__ in, __half* __restrict__ out)
{
    int i = (blockIdx.x * 256 + threadIdx.x) * 4;
    float4 v = *(const float4*)(in + i);
    *(__half2*)(out + i)     = __floats2half2_rn(v.x, v.y);
    *(__half2*)(out + i + 2) = __floats2half2_rn(v.z, v.w);
}

// ---------------------------------------------------------------------------
// Tiled transpose + fp16 convert: out[c][r] = (half)in[r][c].
// ---------------------------------------------------------------------------
__global__ __launch_bounds__(256) void transpose_h_kernel(
    const float* __restrict__ in, __half* __restrict__ out, int R, int Ccols)
{
    __shared__ float t[32][33];
    int c0 = blockIdx.x * 32, r0 = blockIdx.y * 32;
    int x = c0 + threadIdx.x;
#pragma unroll
    for (int i = threadIdx.y; i < 32; i += 8)
        t[i][threadIdx.x] = in[(size_t)(r0 + i) * Ccols + x];
    __syncthreads();
    int ox = r0 + threadIdx.x;
#pragma unroll
    for (int i = threadIdx.y; i < 32; i += 8)
        out[(size_t)(c0 + i) * R + ox] = __float2half_rn(t[threadIdx.x][i]);
}

// ---------------------------------------------------------------------------
// RoPE in-place on fp16 qkv (fp32 math)
// ---------------------------------------------------------------------------
__global__ __launch_bounds__(256) void rope_h_kernel(__half* __restrict__ qkv)
{
    int idx = blockIdx.x * blockDim.x + threadIdx.x;
    int d = idx & 7;
    int h = (idx >> 3) & 15;
    int w = (idx >> 7) & 1;
    int m = idx >> 8;
    int t = m & (SEQ - 1);

    size_t base = (size_t)m * QKV_N + w * C_DIM + h * HD;
    float inv = powf(10000.0f, -(float)d * 0.125f);
    float ang = (float)t * inv;
    float s, c;
    sincosf(ang, &s, &c);
    float x1 = __half2float(qkv[base + d]);
    float x2 = __half2float(qkv[base + d + 8]);
    qkv[base + d]     = __float2half_rn(x1 * c - x2 * s);
    qkv[base + d + 8] = __float2half_rn(x2 * c + x1 * s);
}

// ---------------------------------------------------------------------------
// fp16 tensor-core GEMM with ldmatrix:  C[M,N] = A[M,K] @ Bt[N,K]^T
// CTA 128x128, BK=64, 8 warps (2x4), warp tile 64x32, 3-stage cp.async.
// One __syncthreads per mainloop iter (trailing barrier proven redundant:
// top barrier of iter i orders compute(i-1) reads before load(i+2) writes).
// __launch_bounds__(256,2): 2 CTAs/SM; smem 108KB/CTA -> 216KB/SM (fits).
// ---------------------------------------------------------------------------
constexpr int HG_BM = 128, HG_BN = 128, HG_BK = 64, HG_NST = 3;
constexpr int HG_AP = 72;                    // halves per smem row (64 + 8)
constexpr int HG_AT = 128 * HG_AP;           // 9216 halves (A tile)
constexpr int HG_ST = 2 * HG_AT;             // 18432 halves / stage
constexpr int HG_SMEM_BYTES = HG_NST * HG_ST * 2;   // 110592

template <typename OutT>
__global__ __launch_bounds__(256, 2) void hgemm_kernel(
    const __half* __restrict__ A, const __half* __restrict__ Bt,
    OutT* __restrict__ C, int M, int N, int K)
{
    extern __shared__ __half smh[];
    const uint32_t sb = smem_u32(smh);

    const int tid  = threadIdx.x;
    const int warp = tid >> 5;
    const int lane = tid & 31;
    const int qr   = lane >> 2;
    const int qc   = lane & 3;
    const int m0   = blockIdx.y * HG_BM;
    const int n0   = blockIdx.x * HG_BN;
    const int wm   = (warp >> 2) * 64;
    const int wn   = (warp & 3) * 32;

    // ldmatrix lane offsets (in halves)
    const uint32_t aoff = (uint32_t)(((lane & 7) + ((lane >> 3) & 1) * 8) * HG_AP + (lane >> 4) * 8);
    const uint32_t boff = (uint32_t)(((lane & 7) + (lane >> 4) * 8) * HG_AP + ((lane >> 3) & 1) * 8);

    float acc[4][4][4];
#pragma unroll
    for (int mi = 0; mi < 4; ++mi)
#pragma unroll
        for (int ni = 0; ni < 4; ++ni)
#pragma unroll
            for (int r = 0; r < 4; ++r) acc[mi][ni][r] = 0.f;

    const int NITER = K / HG_BK;

    auto load_stage = [&](int ki) {
        const int k0  = ki * HG_BK;
        const int buf = ki % HG_NST;
        const uint32_t sa  = sb + (uint32_t)buf * HG_ST * 2;
        const uint32_t sbb = sa + HG_AT * 2;
#pragma unroll
        for (int it = 0; it < 4; ++it) {
            int idx = it * 256 + tid;
            int r = idx >> 3, c8 = idx & 7;
            cp_async16(sa + (uint32_t)(r * HG_AP + c8 * 8) * 2,
                       A + (size_t)(m0 + r) * K + k0 + c8 * 8);
        }
#pragma unroll
        for (int it = 0; it < 4; ++it) {
            int idx = it * 256 + tid;
            int r = idx >> 3, c8 = idx & 7;
            cp_async16(sbb + (uint32_t)(r * HG_AP + c8 * 8) * 2,
                       Bt + (size_t)(n0 + r) * K + k0 + c8 * 8);
        }
    };

    load_stage(0); cp_commit();
    load_stage(1); cp_commit();

    for (int i = 0; i < NITER; ++i) {
        cp_wait_group<1>();
        __syncthreads();

        if (i + 2 < NITER) load_stage(i + 2);
        cp_commit();

        const uint32_t sa  = sb + (uint32_t)(i % HG_NST) * HG_ST * 2;
        const uint32_t sbb = sa + HG_AT * 2;

#pragma unroll
        for (int ks = 0; ks < 4; ++ks) {
            uint32_t af[4][4], bf[2][4];
#pragma unroll
            for (int mi = 0; mi < 4; ++mi)
                ldsm_x4(af[mi], sa + (uint32_t)((wm + mi * 16) * HG_AP + ks * 16) * 2 + aoff * 2);
#pragma unroll
            for (int np = 0; np < 2; ++np)
                ldsm_x4(bf[np], sbb + (uint32_t)((wn + np * 16) * HG_AP + ks * 16) * 2 + boff * 2);
#pragma unroll
            for (int mi = 0; mi < 4; ++mi)
#pragma unroll
                for (int np = 0; np < 2; ++np) {
                    mma_f16(acc[mi][np * 2],     af[mi], &bf[np][0]);
                    mma_f16(acc[mi][np * 2 + 1], af[mi], &bf[np][2]);
                }
        }
        // NOTE: no trailing __syncthreads — top barrier of next iter protects
        // buf (i+3)%3 == i%3 from being overwritten while still being read.
    }

    // epilogue
#pragma unroll
    for (int mi = 0; mi < 4; ++mi) {
#pragma unroll
        for (int ni = 0; ni < 4; ++ni) {
            int row = m0 + wm + mi * 16 + qr;
            int col = n0 + wn + ni * 8 + 2 * qc;
            if constexpr (sizeof(OutT) == 2) {
                *(__half2*)&C[(size_t)row * N + col] =
                    __floats2half2_rn(acc[mi][ni][0], acc[mi][ni][1]);
                *(__half2*)&C[(size_t)(row + 8) * N + col] =
                    __floats2half2_rn(acc[mi][ni][2], acc[mi][ni][3]);
            } else {
                *(float2*)&C[(size_t)row * N + col] =
                    make_float2(acc[mi][ni][0], acc[mi][ni][1]);
                *(float2*)&C[(size_t)(row + 8) * N + col] =
                    make_float2(acc[mi][ni][2], acc[mi][ni][3]);
            }
        }
    }
}

// ---------------------------------------------------------------------------
// fp16 flash attention (causal) with ldmatrix + register-resident P.
// CTA: 128 q-rows of one (b,h); 8 warps x 16 q-rows.
// K and V both row-major [64][136] in smem, double-buffered.
// ---------------------------------------------------------------------------
constexpr int AH_KP  = 136;                       // pitch (halves)
constexpr int AH_K0  = 0;
constexpr int AH_K1  = AH_K0 + 64 * AH_KP;        // 8704
constexpr int AH_V0  = AH_K1 + 64 * AH_KP;        // 17408
constexpr int AH_V1  = AH_V0 + 64 * AH_KP;        // 26112
constexpr int AH_SMEM_HALVES = AH_V1 + 64 * AH_KP;   // 34816
constexpr int AH_SMEM_BYTES  = AH_SMEM_HALVES * 2;   // 69632

__global__ __launch_bounds__(256, 1) void attn_kernel(
    const __half* __restrict__ qkv, __half* __restrict__ y)
{
    extern __shared__ __half smh[];
    const uint32_t sb = smem_u32(smh);
    const int tid  = threadIdx.x;
    const int warp = tid >> 5;
    const int lane = tid & 31;
    const int qr   = lane >> 2;
    const int qc   = lane & 3;
    const int qt   = blockIdx.x;            // 128-row q tile, 0..3
    const int bh   = blockIdx.y;
    const int b = bh >> 4, h = bh & 15;

    const __half* baseQ = qkv + (size_t)b * SEQ * QKV_N + h * HD;
    const __half* baseK = baseQ + C_DIM;
    const __half* baseV = baseQ + 2 * C_DIM;
    const int q0 = qt * 128;

    // ldmatrix lane offsets (halves), pitch AH_KP
    const uint32_t aoff = (uint32_t)(((lane & 7) + ((lane >> 3) & 1) * 8) * AH_KP + (lane >> 4) * 8);
    const uint32_t koff = (uint32_t)(((lane & 7) + (lane >> 4) * 8) * AH_KP + ((lane >> 3) & 1) * 8);
    const uint32_t voff = aoff;   // trans V uses the A-style address pattern

    // ---- stage Q (128 x 128 halves) into V0+V1 region
#pragma unroll
    for (int it = 0; it < 8; ++it) {
        int idx = it * 256 + tid;
        int r = idx >> 4, c8 = idx & 15;
        cp_async16(sb + (uint32_t)(AH_V0 + r * AH_KP + c8 * 8) * 2,
                   baseQ + (size_t)(q0 + r) * QKV_N + c8 * 8);
    }
    cp_commit(); cp_wait_group<0>(); __syncthreads();

    // Q fragments via ldmatrix (8 k-steps of 16 over d)
    uint32_t qf[8][4];
    {
        const uint32_t qbase = sb + (uint32_t)(AH_V0 + warp * 16 * AH_KP) * 2 + aoff * 2;
#pragma unroll
        for (int ks = 0; ks < 8; ++ks)
            ldsm_x4(qf[ks], qbase + (uint32_t)(ks * 16) * 2);
    }
    __syncthreads();

    float O[16][4];
#pragma unroll
    for (int dt = 0; dt < 16; ++dt)
#pragma unroll
        for (int r = 0; r < 4; ++r) O[dt][r] = 0.f;
    float m[2] = {-1e30f, -1e30f}, l[2] = {0.f, 0.f};

    const int nkt = 2 * qt + 2;

    auto load_kv = [&](int kt) {
        int buf = kt & 1;
        int t0  = kt * 64;
        const uint32_t kb = sb + (uint32_t)(buf ? AH_K1 : AH_K0) * 2;
        const uint32_t vb = sb + (uint32_t)(buf ? AH_V1 : AH_V0) * 2;
#pragma unroll
        for (int it = 0; it < 4; ++it) {
            int idx = it * 256 + tid;
            int r = idx >> 4, c8 = idx & 15;
            cp_async16(kb + (uint32_t)(r * AH_KP + c8 * 8) * 2,
                       baseK + (size_t)(t0 + r) * QKV_N + c8 * 8);
        }
#pragma unroll
        for (int it = 0; it < 4; ++it) {
            int idx = it * 256 + tid;
            int r = idx >> 4, c8 = idx & 15;
            cp_async16(vb + (uint32_t)(r * AH_KP + c8 * 8) * 2,
                       baseV + (size_t)(t0 + r) * QKV_N + c8 * 8);
        }
    };

    load_kv(0); cp_commit();
    load_kv(1); cp_commit();

    const int qbase_w = q0 + warp * 16;
    const float scl = 0.08838834764831845f;   // 1/sqrt(128)

    for (int kt = 0; kt < nkt; ++kt) {
        cp_wait_group<1>();
        __syncthreads();
        const uint32_t kb = sb + (uint32_t)((kt & 1) ? AH_K1 : AH_K0) * 2;
        const uint32_t vb = sb + (uint32_t)((kt & 1) ? AH_V1 : AH_V0) * 2;

        // ---- S = Q @ K^T  (warp: 16 x 64)
        float s[8][4];
#pragma unroll
        for (int ni = 0; ni < 8; ++ni)
#pragma unroll
            for (int r = 0; r < 4; ++r) s[ni][r] = 0.f;

#pragma unroll
        for (int ks = 0; ks < 8; ++ks) {
#pragma unroll
            for (int np = 0; np < 4; ++np) {
                uint32_t bf[4];
                ldsm_x4(bf, kb + (uint32_t)(np * 16 * AH_KP + ks * 16) * 2 + koff * 2);
                mma_f16(s[np * 2],     qf[ks], &bf[0]);
                mma_f16(s[np * 2 + 1], qf[ks], &bf[2]);
            }
        }

        // ---- scale + causal mask + online softmax (P stays in registers)
        const bool domask = (kt * 64 + 63 > qbase_w);
#pragma unroll
        for (int r = 0; r < 2; ++r) {
            int qg = qbase_w + qr + 8 * r;
            float mx = -1e30f;
#pragma unroll
            for (int ni = 0; ni < 8; ++ni) {
#pragma unroll
                for (int v = 0; v < 2; ++v) {
                    float val = s[ni][r * 2 + v] * scl;
                    if (domask) {
                        int kg = kt * 64 + ni * 8 + 2 * qc + v;
                        if (kg > qg) val = -1e30f;
                    }
                    s[ni][r * 2 + v] = val;
                    mx = fmaxf(mx, val);
                }
            }
            mx = fmaxf(mx, __shfl_xor_sync(0xffffffffu, mx, 1));
            mx = fmaxf(mx, __shfl_xor_sync(0xffffffffu, mx, 2));
            float mnew  = fmaxf(m[r], mx);
            float alpha = __expf(m[r] - mnew);
            float sum = 0.f;
#pragma unroll
            for (int ni = 0; ni < 8; ++ni) {
                float p0 = __expf(s[ni][r * 2]     - mnew);
                float p1 = __expf(s[ni][r * 2 + 1] - mnew);
                sum += p0 + p1;
                s[ni][r * 2]     = p0;
                s[ni][r * 2 + 1] = p1;
            }
            sum += __shfl_xor_sync(0xffffffffu, sum, 1);
            sum += __shfl_xor_sync(0xffffffffu, sum, 2);
            l[r] = l[r] * alpha + sum;
            m[r] = mnew;
#pragma unroll
            for (int dt = 0; dt < 16; ++dt) {
                O[dt][r * 2]     *= alpha;
                O[dt][r * 2 + 1] *= alpha;
            }
        }

        // ---- O += P @ V  (P from accumulator frags; V via ldmatrix.trans)
#pragma unroll
        for (int kk = 0; kk < 4; ++kk) {
            uint32_t af[4] = {
                pack_h2(s[2 * kk][0],     s[2 * kk][1]),
                pack_h2(s[2 * kk][2],     s[2 * kk][3]),
                pack_h2(s[2 * kk + 1][0], s[2 * kk + 1][1]),
                pack_h2(s[2 * kk + 1][2], s[2 * kk + 1][3]) };
#pragma unroll
            for (int dp = 0; dp < 8; ++dp) {
                uint32_t bf[4];
                ldsm_x4_t(bf, vb + (uint32_t)(kk * 16 * AH_KP + dp * 16) * 2 + voff * 2);
                mma_f16(O[dp * 2],     af, &bf[0]);
                mma_f16(O[dp * 2 + 1], af, &bf[2]);
            }
        }

        __syncthreads();
        if (kt + 2 < nkt) load_kv(kt + 2);
        cp_commit();
    }

    // ---- finalize, write y (fp16)
#pragma unroll
    for (int r = 0; r < 2; ++r) {
        float inv = 1.0f / l[r];
        int row = qbase_w + qr + 8 * r;
        __half* yp = y + (size_t)(b * SEQ + row) * C_DIM + h * HD;
#pragma unroll
        for (int dt = 0; dt < 16; ++dt)
            *(__half2*)&yp[dt * 8 + 2 * qc] =
                __floats2half2_rn(O[dt][r * 2] * inv, O[dt][r * 2 + 1] * inv);
    }
}

// ---------------------------------------------------------------------------
extern "C" void kernel_launch(void* const* d_in, const int* in_sizes, int n_in,
                              void* d_out, int out_size)
{
    const float* x    = (const float*)d_in[0];
    const float* Wqkv = (const float*)d_in[1];
    const float* Wout = (const float*)d_in[2];
    float* out = (float*)d_out;

    __half *xh, *qkvh, *yh, *wqkvTh, *woutTh;
    cudaGetSymbolAddress((void**)&xh,     g_xh);
    cudaGetSymbolAddress((void**)&qkvh,   g_qkvh);
    cudaGetSymbolAddress((void**)&yh,     g_yh);
    cudaGetSymbolAddress((void**)&wqkvTh, g_WqkvTh);
    cudaGetSymbolAddress((void**)&woutTh, g_WoutTh);

    static bool attr_set = false;
    if (!attr_set) {
        cudaFuncSetAttribute(hgemm_kernel<__half>, cudaFuncAttributeMaxDynamicSharedMemorySize, HG_SMEM_BYTES);
        cudaFuncSetAttribute(hgemm_kernel<float>,  cudaFuncAttributeMaxDynamicSharedMemorySize, HG_SMEM_BYTES);
        cudaFuncSetAttribute(attn_kernel,          cudaFuncAttributeMaxDynamicSharedMemorySize, AH_SMEM_BYTES);
        attr_set = true;
    }

    // 0) convert x -> fp16; transpose+convert weights -> [N,K] fp16
    f2h_kernel<<<(MROWS * C_DIM / 4) / 256, 256>>>(x, xh);
    transpose_h_kernel<<<dim3(QKV_N / 32, C_DIM / 32), dim3(32, 8)>>>(Wqkv, wqkvTh, C_DIM, QKV_N);
    transpose_h_kernel<<<dim3(C_DIM / 32, C_DIM / 32), dim3(32, 8)>>>(Wout, woutTh, C_DIM, C_DIM);

    // 1) qkv = x @ Wqkv  (fp16 MMA + ldmatrix, BK=64, 1 barrier/iter)
    hgemm_kernel<__half><<<dim3(QKV_N / HG_BN, MROWS / HG_BM), 256, HG_SMEM_BYTES>>>(
        xh, wqkvTh, qkvh, MROWS, QKV_N, C_DIM);

    // 2) RoPE in-place on q,k (fp16)
    rope_h_kernel<<<(MROWS * 2 * NH * 8) / 256, 256>>>(qkvh);

    // 3) causal flash attention (fp16 MMA + ldmatrix, register P) -> y fp16
    attn_kernel<<<dim3(SEQ / 128, NB * NH), 256, AH_SMEM_BYTES>>>(qkvh, yh);

    // 4) out = y @ Wout  (fp16 MMA + ldmatrix, fp32 out)
    hgemm_kernel<float><<<dim3(C_DIM / HG_BN, MROWS / HG_BM), 256, HG_SMEM_BYTES>>>(
        yh, woutTh, out, MROWS, C_DIM, C_DIM);
}